// round 1
// baseline (speedup 1.0000x reference)
#include <cuda_runtime.h>
#include <math.h>

#define BB 32
#define TT 24
#define NN 1024
#define KC 32

// ---------------- scratch (single device global, sliced by offsets) ------------
#define OFF_H    0            // (B,N,32)  [h1 | h2]
#define OFF_Y32  1048576      // (B,N,32)  [A@h1 | A@h2]
#define OFF_RH   2097152      // (B,N,16)  r*h  (GEMM input)
#define OFF_ARH  2621440      // (B,N,16)  A@(r*h)   (also A@h2 at the end)
#define OFF_AX1  3145728      // (B,N,16)  A@h1'
#define OFF_U    3670016      // (B,N,16)  update gate
#define OFF_AX   4194304      // 3 x (B,N,16) A@x_t for all 24 t (8 t per group)
#define OFF_XG   5767168      // (B,N,16)  gather staging
#define OFF_RS   6291456      // (B,N)     rowsum(A)
#define OFF_TVF  6324224      // (B,2)     trend/feat contribution to final GCN
#define SCRATCH_FLOATS 6324288

__device__ float d_scratch[SCRATCH_FLOATS];

__device__ __forceinline__ float sigf(float x) { return 1.0f / (1.0f + expf(-x)); }

__device__ __forceinline__ void cpa16(void* sm, const void* gm) {
    unsigned sa = (unsigned)__cvta_generic_to_shared(sm);
    asm volatile("cp.async.cg.shared.global [%0], [%1], 16;" :: "r"(sa), "l"(gm) : "memory");
}
#define CP_COMMIT() asm volatile("cp.async.commit_group;" ::: "memory")
#define CP_WAIT(n)  asm volatile("cp.async.wait_group %0;" :: "n"(n) : "memory")

// =============== skinny batched GEMM: Y[b,i,c] = sum_j A[b,i,j] * X[b,j,c] =====
// CTA: 128 rows x C cols, K streamed in KC=32 chunks, cp.async double buffer.
// Inner loop uses packed fma.rn.f32x2 (2 FMA lanes / instr) — required for full
// fp32 rate on sm_103a (3-reg FFMA is half-rate per SASS_QUICKREF).
template <int C>
__global__ __launch_bounds__(128) void gemmK(const float* __restrict__ A,
                                             int xoff, int xs, int xo, int yoff) {
    __shared__ __align__(16) float As[2][128][KC + 4];
    __shared__ __align__(16) float Xs[2][KC][C];

    const int b    = blockIdx.y;
    const int row0 = blockIdx.x * 128;
    const int tid  = threadIdx.x;

    const float* Ab = A + ((size_t)b * NN + row0) * NN;
    const float* Xb = d_scratch + xoff + (size_t)b * NN * xs + xo;
    float*       Y  = d_scratch + yoff;

    unsigned long long acc[C / 2];
#pragma unroll
    for (int i = 0; i < C / 2; i++) acc[i] = 0ull;

    auto load_tiles = [&](int buf, int k0) {
#pragma unroll
        for (int i = 0; i < 8; i++) {               // A tile: 128 x 32 floats
            int ch = tid + i * 128;
            int r  = ch >> 3, kk = ch & 7;
            cpa16(&As[buf][r][kk * 4], Ab + (size_t)r * NN + k0 + kk * 4);
        }
#pragma unroll
        for (int i = 0; i < C / 16; i++) {          // X tile: 32 x C floats
            int ch = tid + i * 128;
            int r  = ch / (C / 4), cc = ch % (C / 4);
            cpa16(&Xs[buf][r][cc * 4], Xb + (size_t)(k0 + r) * xs + cc * 4);
        }
    };

    load_tiles(0, 0);
    CP_COMMIT();

    for (int kt = 0; kt < NN / KC; kt++) {
        int cur = kt & 1;
        if (kt + 1 < NN / KC) {
            load_tiles(cur ^ 1, (kt + 1) * KC);
            CP_COMMIT();
            CP_WAIT(1);
        } else {
            CP_WAIT(0);
        }
        __syncthreads();

        const float* ar = &As[cur][tid][0];
#pragma unroll
        for (int k4 = 0; k4 < KC; k4 += 4) {
            float4 a4 = *(const float4*)(ar + k4);
            float av[4] = {a4.x, a4.y, a4.z, a4.w};
#pragma unroll
            for (int q = 0; q < 4; q++) {
                unsigned long long aa;
                unsigned au = __float_as_uint(av[q]);
                asm("mov.b64 %0, {%1, %1};" : "=l"(aa) : "r"(au));
                const ulonglong2* xr = (const ulonglong2*)&Xs[cur][k4 + q][0];
#pragma unroll
                for (int i = 0; i < C / 4; i++) {
                    ulonglong2 xv = xr[i];
                    asm("fma.rn.f32x2 %0, %1, %2, %0;" : "+l"(acc[2 * i])     : "l"(aa), "l"(xv.x));
                    asm("fma.rn.f32x2 %0, %1, %2, %0;" : "+l"(acc[2 * i + 1]) : "l"(aa), "l"(xv.y));
                }
            }
        }
        __syncthreads();
    }

    float y[C];
#pragma unroll
    for (int i = 0; i < C / 2; i++) {
        unsigned lo, hi;
        asm("mov.b64 {%0, %1}, %2;" : "=r"(lo), "=r"(hi) : "l"(acc[i]));
        y[2 * i]     = __uint_as_float(lo);
        y[2 * i + 1] = __uint_as_float(hi);
    }
    float4* yp = (float4*)(Y + ((size_t)b * NN + row0 + tid) * C);
#pragma unroll
    for (int i = 0; i < C / 4; i++)
        yp[i] = make_float4(y[4 * i], y[4 * i + 1], y[4 * i + 2], y[4 * i + 3]);
}

// ================================ small kernels ================================

__global__ __launch_bounds__(256) void zeroHK() {
    int i = blockIdx.x * 256 + threadIdx.x;
    d_scratch[OFF_H + i] = 0.0f;
}

// gather recent_data (B,T,N,2) -> Xg (B,N,16) for t-group g (8 timesteps)
__global__ __launch_bounds__(256) void gatherK(const float* __restrict__ recent, int g) {
    int r = blockIdx.x * 256 + threadIdx.x;          // b*N + n
    int b = r >> 10, n = r & 1023;
    const float2* rp = (const float2*)recent;
    float2* xp = (float2*)(d_scratch + OFF_XG + (size_t)r * 16);
#pragma unroll
    for (int p = 0; p < 8; p++)
        xp[p] = rp[((size_t)(b * TT + g * 8 + p)) * NN + n];
}

__global__ __launch_bounds__(256) void rowsumK(const float* __restrict__ A) {
    int warp = (blockIdx.x * blockDim.x + threadIdx.x) >> 5;
    int lane = threadIdx.x & 31;
    const float4* ap = (const float4*)(A + (size_t)warp * NN);
    float s = 0.0f;
#pragma unroll
    for (int i = lane; i < 256; i += 32) {
        float4 v = ap[i];
        s += (v.x + v.y) + (v.z + v.w);
    }
#pragma unroll
    for (int o = 16; o; o >>= 1) s += __shfl_xor_sync(~0u, s, o);
    if (!lane) d_scratch[OFF_RS + warp] = s;
}

// 2-layer LSTM over trend + feat FF + fold into final-GCN constants tvf (B,2)
__global__ __launch_bounds__(1024) void prepK(
    const float* __restrict__ trend, const float* __restrict__ tf,
    const float* __restrict__ Wih0, const float* __restrict__ Whh0,
    const float* __restrict__ bih0, const float* __restrict__ bhh0,
    const float* __restrict__ Wih1, const float* __restrict__ Whh1,
    const float* __restrict__ bih1, const float* __restrict__ bhh1,
    const float* __restrict__ ffW, const float* __restrict__ ffb,
    const float* __restrict__ gcnW) {
    __shared__ float h1s[32][32], c1s[32][32], h2s[32][32], c2s[32][32], feats[32][32];
    int tid = threadIdx.x;
    int b = tid >> 5, j = tid & 31;
    h1s[b][j] = 0.f; c1s[b][j] = 0.f; h2s[b][j] = 0.f; c2s[b][j] = 0.f;
    __syncthreads();

    for (int t = 0; t < TT; t++) {
        float x0 = trend[(b * TT + t) * 2 + 0];
        float x1 = trend[(b * TT + t) * 2 + 1];
        float g0[4];
#pragma unroll
        for (int g = 0; g < 4; g++) {
            int idx = g * 32 + j;
            float s = bih0[idx] + bhh0[idx] + Wih0[idx * 2] * x0 + Wih0[idx * 2 + 1] * x1;
            for (int k = 0; k < 32; k++) s += Whh0[idx * 32 + k] * h1s[b][k];
            g0[g] = s;
        }
        float c1 = sigf(g0[1]) * c1s[b][j] + sigf(g0[0]) * tanhf(g0[2]);
        float h1 = sigf(g0[3]) * tanhf(c1);
        __syncthreads();
        h1s[b][j] = h1; c1s[b][j] = c1;
        __syncthreads();

        float g1[4];
#pragma unroll
        for (int g = 0; g < 4; g++) {
            int idx = g * 32 + j;
            float s = bih1[idx] + bhh1[idx];
            for (int k = 0; k < 32; k++)
                s += Wih1[idx * 32 + k] * h1s[b][k] + Whh1[idx * 32 + k] * h2s[b][k];
            g1[g] = s;
        }
        float c2 = sigf(g1[1]) * c2s[b][j] + sigf(g1[0]) * tanhf(g1[2]);
        float h2 = sigf(g1[3]) * tanhf(c2);
        __syncthreads();
        h2s[b][j] = h2; c2s[b][j] = c2;
        __syncthreads();
    }

    // feat = relu(tf @ ffW^T + ffb)
    float s = ffb[j];
    for (int k = 0; k < 31; k++) s += tf[b * 31 + k] * ffW[j * 31 + k];
    feats[b][j] = fmaxf(s, 0.f);
    __syncthreads();

    if (tid < 64) {
        int bb = tid >> 1, f = tid & 1;
        float s2 = 0.f;
        for (int c = 0; c < 32; c++)
            s2 += h2s[bb][c] * gcnW[f * 80 + 16 + c] + feats[bb][c] * gcnW[f * 80 + 48 + c];
        d_scratch[OFF_TVF + bb * 2 + f] = s2;
    }
}

// GRU1 r/u gates: inputs [A@x_t(2) | A@h1(16)] -> u1, r1*h1
__global__ __launch_bounds__(256) void gates1K(const float* __restrict__ rW, const float* __restrict__ rb,
                                               const float* __restrict__ uW, const float* __restrict__ ub,
                                               int g, int p) {
    int r = blockIdx.x * 256 + threadIdx.x;
    const float* ax  = d_scratch + OFF_AX + (size_t)g * 524288 + (size_t)r * 16 + p * 2;
    const float* ah1 = d_scratch + OFF_Y32 + (size_t)r * 32;
    const float* h1  = d_scratch + OFF_H   + (size_t)r * 32;
    float xh[18];
    xh[0] = ax[0]; xh[1] = ax[1];
#pragma unroll
    for (int k = 0; k < 16; k++) xh[2 + k] = ah1[k];
#pragma unroll
    for (int j = 0; j < 16; j++) {
        float sr = rb[j], su = ub[j];
#pragma unroll
        for (int k = 0; k < 18; k++) { sr += xh[k] * rW[j * 18 + k]; su += xh[k] * uW[j * 18 + k]; }
        d_scratch[OFF_U  + (size_t)r * 16 + j] = sigf(su);
        d_scratch[OFF_RH + (size_t)r * 16 + j] = sigf(sr) * h1[j];
    }
}

// GRU1 candidate + state update: h1' = u1*h1 + (1-u1)*tanh([A@x|A@(r1 h1)] @ cW^T)
__global__ __launch_bounds__(256) void gates2K(const float* __restrict__ cW, const float* __restrict__ cb,
                                               int g, int p) {
    int r = blockIdx.x * 256 + threadIdx.x;
    const float* ax  = d_scratch + OFF_AX + (size_t)g * 524288 + (size_t)r * 16 + p * 2;
    const float* arh = d_scratch + OFF_ARH + (size_t)r * 16;
    const float* u   = d_scratch + OFF_U   + (size_t)r * 16;
    float xh[18];
    xh[0] = ax[0]; xh[1] = ax[1];
#pragma unroll
    for (int k = 0; k < 16; k++) xh[2 + k] = arh[k];
#pragma unroll
    for (int j = 0; j < 16; j++) {
        float s = cb[j];
#pragma unroll
        for (int k = 0; k < 18; k++) s += xh[k] * cW[j * 18 + k];
        float c = tanhf(s);
        float h1 = d_scratch[OFF_H + (size_t)r * 32 + j];
        d_scratch[OFF_H + (size_t)r * 32 + j] = u[j] * h1 + (1.f - u[j]) * c;
    }
}

// GRU2 r/u gates: inputs [A@h1'(16) | A@h2(16)] -> u2, r2*h2
__global__ __launch_bounds__(256) void gates3K(const float* __restrict__ rW, const float* __restrict__ rb,
                                               const float* __restrict__ uW, const float* __restrict__ ub) {
    int r = blockIdx.x * 256 + threadIdx.x;
    const float* ax1 = d_scratch + OFF_AX1 + (size_t)r * 16;
    const float* ah2 = d_scratch + OFF_Y32 + (size_t)r * 32 + 16;
    const float* h2  = d_scratch + OFF_H   + (size_t)r * 32 + 16;
    float xh[32];
#pragma unroll
    for (int k = 0; k < 16; k++) { xh[k] = ax1[k]; xh[16 + k] = ah2[k]; }
#pragma unroll
    for (int j = 0; j < 16; j++) {
        float sr = rb[j], su = ub[j];
#pragma unroll
        for (int k = 0; k < 32; k++) { sr += xh[k] * rW[j * 32 + k]; su += xh[k] * uW[j * 32 + k]; }
        d_scratch[OFF_U  + (size_t)r * 16 + j] = sigf(su);
        d_scratch[OFF_RH + (size_t)r * 16 + j] = sigf(sr) * h2[j];
    }
}

// GRU2 candidate + state update
__global__ __launch_bounds__(256) void gates4K(const float* __restrict__ cW, const float* __restrict__ cb) {
    int r = blockIdx.x * 256 + threadIdx.x;
    const float* ax1 = d_scratch + OFF_AX1 + (size_t)r * 16;
    const float* arh = d_scratch + OFF_ARH + (size_t)r * 16;
    const float* u   = d_scratch + OFF_U   + (size_t)r * 16;
    float xh[32];
#pragma unroll
    for (int k = 0; k < 16; k++) { xh[k] = ax1[k]; xh[16 + k] = arh[k]; }
#pragma unroll
    for (int j = 0; j < 16; j++) {
        float s = cb[j];
#pragma unroll
        for (int k = 0; k < 32; k++) s += xh[k] * cW[j * 32 + k];
        float c = tanhf(s);
        float h2 = d_scratch[OFF_H + (size_t)r * 32 + 16 + j];
        d_scratch[OFF_H + (size_t)r * 32 + 16 + j] = u[j] * h2 + (1.f - u[j]) * c;
    }
}

// out[b,n,f] = tanh( (A@h2) . gcnW[f,0:16] + rowsum*tvf[b,f] + gcn_b[f] )
__global__ __launch_bounds__(256) void finalK(const float* __restrict__ gcnW,
                                              const float* __restrict__ gcnb,
                                              float* __restrict__ out) {
    int r = blockIdx.x * 256 + threadIdx.x;
    int b = r >> 10;
    const float* arec = d_scratch + OFF_ARH + (size_t)r * 16;
    float rs = d_scratch[OFF_RS + r];
#pragma unroll
    for (int f = 0; f < 2; f++) {
        float s = gcnb[f] + rs * d_scratch[OFF_TVF + b * 2 + f];
#pragma unroll
        for (int c = 0; c < 16; c++) s += arec[c] * gcnW[f * 80 + c];
        out[r * 2 + f] = tanhf(s);
    }
}

// ================================== launcher ===================================

extern "C" void kernel_launch(void* const* d_in, const int* in_sizes, int n_in,
                              void* d_out, int out_size) {
    const float* recent = (const float*)d_in[0];
    const float* trend  = (const float*)d_in[1];
    const float* A      = (const float*)d_in[2];
    const float* tf     = (const float*)d_in[3];
    const float* g1rW = (const float*)d_in[4],  *g1rb = (const float*)d_in[5];
    const float* g1uW = (const float*)d_in[6],  *g1ub = (const float*)d_in[7];
    const float* g1cW = (const float*)d_in[8],  *g1cb = (const float*)d_in[9];
    const float* g2rW = (const float*)d_in[10], *g2rb = (const float*)d_in[11];
    const float* g2uW = (const float*)d_in[12], *g2ub = (const float*)d_in[13];
    const float* g2cW = (const float*)d_in[14], *g2cb = (const float*)d_in[15];
    const float* Wih0 = (const float*)d_in[16], *Whh0 = (const float*)d_in[17];
    const float* bih0 = (const float*)d_in[18], *bhh0 = (const float*)d_in[19];
    const float* Wih1 = (const float*)d_in[20], *Whh1 = (const float*)d_in[21];
    const float* bih1 = (const float*)d_in[22], *bhh1 = (const float*)d_in[23];
    const float* ffW  = (const float*)d_in[24], *ffb  = (const float*)d_in[25];
    const float* gcnW = (const float*)d_in[26], *gcnb = (const float*)d_in[27];
    float* out = (float*)d_out;

    dim3 gg(8, 32);        // (N/128 row tiles, B)
    dim3 ge(128);          // elementwise grid: B*N / 256

    zeroHK<<<4096, 256>>>();
    prepK<<<1, 1024>>>(trend, tf, Wih0, Whh0, bih0, bhh0,
                       Wih1, Whh1, bih1, bhh1, ffW, ffb, gcnW);
    rowsumK<<<4096, 256>>>(A);

    // Hoisted A @ x_t for all 24 timesteps (3 groups of 8)
    for (int g = 0; g < 3; g++) {
        gatherK<<<ge, 256>>>(recent, g);
        gemmK<16><<<gg, 128>>>(A, OFF_XG, 16, 0, OFF_AX + g * 524288);
    }

    for (int t = 0; t < TT; t++) {
        int g = t >> 3, p = t & 7;
        gemmK<32><<<gg, 128>>>(A, OFF_H, 32, 0, OFF_Y32);    // [A@h1 | A@h2]
        gates1K<<<ge, 256>>>(g1rW, g1rb, g1uW, g1ub, g, p);
        gemmK<16><<<gg, 128>>>(A, OFF_RH, 16, 0, OFF_ARH);   // A@(r1*h1)
        gates2K<<<ge, 256>>>(g1cW, g1cb, g, p);
        gemmK<16><<<gg, 128>>>(A, OFF_H, 32, 0, OFF_AX1);    // A@h1'
        gates3K<<<ge, 256>>>(g2rW, g2rb, g2uW, g2ub);
        gemmK<16><<<gg, 128>>>(A, OFF_RH, 16, 0, OFF_ARH);   // A@(r2*h2)
        gates4K<<<ge, 256>>>(g2cW, g2cb);
    }

    gemmK<16><<<gg, 128>>>(A, OFF_H, 32, 16, OFF_ARH);       // A@h2 (recent part)
    finalK<<<ge, 256>>>(gcnW, gcnb, out);
}

// round 2
// speedup vs baseline: 1.8492x; 1.8492x over previous
#include <cuda_runtime.h>
#include <cuda_bf16.h>
#include <math.h>

#define BB 32
#define TT 24
#define NN 1024
#define KC 64

// ---------------- fp32 scratch ------------
#define OFF_H    0            // (B,N,32)  [h1 | h2] fp32 master
#define OFF_Y32  1048576      // (B,N,32)  [A@h1 | A@h2]
#define OFF_ARH  2621440      // (B,N,16)  A@(r*h)  (also A@h2 at the end)
#define OFF_AX1  3145728      // (B,N,16)  A@h1'
#define OFF_U    3670016      // (B,N,16)  update gate
#define OFF_AX   4194304      // 3 x (B,N,16) A@x_t for all 24 t
#define OFF_RS   6291456      // (B,N)     rowsum(A)
#define OFF_TVF  6324224      // (B,2)     trend/feat contribution
#define SCRATCH_FLOATS 6324288

__device__ float d_scratch[SCRATCH_FLOATS];
// A in bf16: 64 MB, fits L2 (126 MB) -> all GEMM sweeps become L2-resident
__device__ __nv_bfloat16 d_Abf[(size_t)BB * NN * NN];
// X operands, bf16 TRANSPOSED: [b][col][n]; cols 0-31: [h1|h2], 32-47: r*h, 48-63: x-gather
__device__ __nv_bfloat16 d_xbf[(size_t)BB * 64 * NN];

__device__ __forceinline__ float sigf(float x) { return 1.0f / (1.0f + expf(-x)); }

__device__ __forceinline__ void cpa16(void* sm, const void* gm) {
    unsigned sa = (unsigned)__cvta_generic_to_shared(sm);
    asm volatile("cp.async.cg.shared.global [%0], [%1], 16;" :: "r"(sa), "l"(gm) : "memory");
}
#define CP_COMMIT() asm volatile("cp.async.commit_group;" ::: "memory")
#define CP_WAIT(n)  asm volatile("cp.async.wait_group %0;" :: "n"(n) : "memory")

// =============== skinny batched GEMM via bf16 HMMA ============================
// Y[b,i,c] = sum_j A[b,i,j] * X[b,j,c], rows tiled 128/CTA (4 warps x 32 rows),
// K streamed in KC=64 bf16 chunks (cp.async double buffer), X read from the
// transposed bf16 buffer so both A and B fragments come from ldmatrix.
// smem rows padded to 36 words (144B) -> 16B-aligned cp.async + conflict-free ldmatrix.
template <int C>
__global__ __launch_bounds__(128) void gemmT(int xcol0, int yoff) {
    constexpr int SW = 36;                               // u32 words per smem row
    __shared__ __align__(16) unsigned As[2][128 * SW];
    __shared__ __align__(16) unsigned Xs[2][C * SW];

    const int b    = blockIdx.y;
    const int row0 = blockIdx.x * 128;
    const int tid  = threadIdx.x, w = tid >> 5, lane = tid & 31;

    const __nv_bfloat16* Ab = d_Abf + (size_t)(b * NN + row0) * NN;
    const __nv_bfloat16* Xb = d_xbf + (size_t)(b * 64 + xcol0) * NN;

    float acc[2][C / 8][4];
#pragma unroll
    for (int mt = 0; mt < 2; mt++)
#pragma unroll
        for (int nt = 0; nt < C / 8; nt++)
#pragma unroll
            for (int q = 0; q < 4; q++) acc[mt][nt][q] = 0.f;

    auto load = [&](int buf, int k0) {
#pragma unroll
        for (int i = 0; i < 8; i++) {                    // A: 128 rows x 8 16B-chunks
            int ch = tid + i * 128, r = ch >> 3, j = ch & 7;
            cpa16(&As[buf][r * SW + j * 4], Ab + (size_t)r * NN + k0 + j * 8);
        }
#pragma unroll
        for (int i = 0; i < C / 16; i++) {               // X^T: C rows x 8 chunks
            int ch = tid + i * 128, r = ch >> 3, j = ch & 7;
            cpa16(&Xs[buf][r * SW + j * 4], Xb + (size_t)r * NN + k0 + j * 8);
        }
    };

    // lane-constant ldmatrix byte offsets
    const unsigned aoff = ((unsigned)(w * 32 + (lane & 15)) * SW + (lane >> 4) * 4) * 4;
    const unsigned boff = ((unsigned)(lane & 7) * SW + ((lane >> 3) & 1) * 4) * 4;

    load(0, 0);
    CP_COMMIT();

    for (int kt = 0; kt < NN / KC; kt++) {
        int cur = kt & 1;
        if (kt + 1 < NN / KC) {
            load(cur ^ 1, (kt + 1) * KC);
            CP_COMMIT();
            CP_WAIT(1);
        } else {
            CP_WAIT(0);
        }
        __syncthreads();

        unsigned aB = (unsigned)__cvta_generic_to_shared(&As[cur][0]);
        unsigned xB = (unsigned)__cvta_generic_to_shared(&Xs[cur][0]);

#pragma unroll
        for (int ks = 0; ks < KC / 16; ks++) {
            const unsigned kb = (unsigned)ks * 8 * 4;    // 8 words per k16 step
            unsigned bf[C / 8][2];
#pragma unroll
            for (int nt = 0; nt < C / 8; nt++) {
                unsigned ad = xB + boff + (unsigned)nt * 8 * SW * 4 + kb;
                asm volatile("ldmatrix.sync.aligned.m8n8.x2.shared.b16 {%0,%1}, [%2];"
                             : "=r"(bf[nt][0]), "=r"(bf[nt][1]) : "r"(ad));
            }
#pragma unroll
            for (int mt = 0; mt < 2; mt++) {
                unsigned a0, a1, a2, a3;
                unsigned ad = aB + aoff + (unsigned)mt * 16 * SW * 4 + kb;
                asm volatile("ldmatrix.sync.aligned.m8n8.x4.shared.b16 {%0,%1,%2,%3}, [%4];"
                             : "=r"(a0), "=r"(a1), "=r"(a2), "=r"(a3) : "r"(ad));
#pragma unroll
                for (int nt = 0; nt < C / 8; nt++) {
                    asm volatile(
                        "mma.sync.aligned.m16n8k16.row.col.f32.bf16.bf16.f32 "
                        "{%0,%1,%2,%3},{%4,%5,%6,%7},{%8,%9},{%0,%1,%2,%3};"
                        : "+f"(acc[mt][nt][0]), "+f"(acc[mt][nt][1]),
                          "+f"(acc[mt][nt][2]), "+f"(acc[mt][nt][3])
                        : "r"(a0), "r"(a1), "r"(a2), "r"(a3),
                          "r"(bf[nt][0]), "r"(bf[nt][1]));
                }
            }
        }
        __syncthreads();
    }

    const int g = lane >> 2, c2 = (lane & 3) * 2;
    float* Y = d_scratch + yoff + (size_t)b * NN * C;
#pragma unroll
    for (int mt = 0; mt < 2; mt++) {
        int r = row0 + w * 32 + mt * 16 + g;
#pragma unroll
        for (int nt = 0; nt < C / 8; nt++) {
            *(float2*)(Y + (size_t)r * C + nt * 8 + c2)       = make_float2(acc[mt][nt][0], acc[mt][nt][1]);
            *(float2*)(Y + (size_t)(r + 8) * C + nt * 8 + c2) = make_float2(acc[mt][nt][2], acc[mt][nt][3]);
        }
    }
}

// ================================ small kernels ================================

__global__ __launch_bounds__(256) void convAK(const float* __restrict__ A) {
    size_t i = ((size_t)blockIdx.x * 256 + threadIdx.x) * 8;
    float4 v0 = *(const float4*)(A + i);
    float4 v1 = *(const float4*)(A + i + 4);
    __nv_bfloat162 b0 = __float22bfloat162_rn(make_float2(v0.x, v0.y));
    __nv_bfloat162 b1 = __float22bfloat162_rn(make_float2(v0.z, v0.w));
    __nv_bfloat162 b2 = __float22bfloat162_rn(make_float2(v1.x, v1.y));
    __nv_bfloat162 b3 = __float22bfloat162_rn(make_float2(v1.z, v1.w));
    uint4 o;
    o.x = *(unsigned*)&b0; o.y = *(unsigned*)&b1; o.z = *(unsigned*)&b2; o.w = *(unsigned*)&b3;
    *(uint4*)(d_Abf + i) = o;
}

__global__ __launch_bounds__(256) void zeroHK() {
    int i = blockIdx.x * 256 + threadIdx.x;
    d_scratch[OFF_H + i] = 0.0f;
}
__global__ __launch_bounds__(256) void zeroXK() {
    size_t i = ((size_t)blockIdx.x * 256 + threadIdx.x) * 8;
    *(uint4*)(d_xbf + i) = make_uint4(0, 0, 0, 0);
}

// gather recent_data (B,T,N,2) -> xbf cols 48..63 (transposed) for t-group g
__global__ __launch_bounds__(256) void gatherK(const float* __restrict__ recent, int g) {
    int r = blockIdx.x * 256 + threadIdx.x;
    int b = r >> 10, n = r & 1023;
    const float2* rp = (const float2*)recent;
    __nv_bfloat16* xb = d_xbf + ((size_t)b * 64 + 48) * NN + n;
#pragma unroll
    for (int p = 0; p < 8; p++) {
        float2 v = rp[((size_t)(b * TT + g * 8 + p)) * NN + n];
        xb[(size_t)(p * 2) * NN]     = __float2bfloat16_rn(v.x);
        xb[(size_t)(p * 2 + 1) * NN] = __float2bfloat16_rn(v.y);
    }
}

__global__ __launch_bounds__(256) void rowsumK(const float* __restrict__ A) {
    int warp = (blockIdx.x * blockDim.x + threadIdx.x) >> 5;
    int lane = threadIdx.x & 31;
    const float4* ap = (const float4*)(A + (size_t)warp * NN);
    float s = 0.0f;
#pragma unroll
    for (int i = lane; i < 256; i += 32) {
        float4 v = ap[i];
        s += (v.x + v.y) + (v.z + v.w);
    }
#pragma unroll
    for (int o = 16; o; o >>= 1) s += __shfl_xor_sync(~0u, s, o);
    if (!lane) d_scratch[OFF_RS + warp] = s;
}

// 2-layer LSTM over trend + feat FF + fold into final-GCN constants tvf (B,2)
__global__ __launch_bounds__(1024) void prepK(
    const float* __restrict__ trend, const float* __restrict__ tf,
    const float* __restrict__ Wih0, const float* __restrict__ Whh0,
    const float* __restrict__ bih0, const float* __restrict__ bhh0,
    const float* __restrict__ Wih1, const float* __restrict__ Whh1,
    const float* __restrict__ bih1, const float* __restrict__ bhh1,
    const float* __restrict__ ffW, const float* __restrict__ ffb,
    const float* __restrict__ gcnW) {
    __shared__ float h1s[32][32], c1s[32][32], h2s[32][32], c2s[32][32], feats[32][32];
    int tid = threadIdx.x;
    int b = tid >> 5, j = tid & 31;
    h1s[b][j] = 0.f; c1s[b][j] = 0.f; h2s[b][j] = 0.f; c2s[b][j] = 0.f;
    __syncthreads();

    for (int t = 0; t < TT; t++) {
        float x0 = trend[(b * TT + t) * 2 + 0];
        float x1 = trend[(b * TT + t) * 2 + 1];
        float g0[4];
#pragma unroll
        for (int g = 0; g < 4; g++) {
            int idx = g * 32 + j;
            float s = bih0[idx] + bhh0[idx] + Wih0[idx * 2] * x0 + Wih0[idx * 2 + 1] * x1;
            for (int k = 0; k < 32; k++) s += Whh0[idx * 32 + k] * h1s[b][k];
            g0[g] = s;
        }
        float c1 = sigf(g0[1]) * c1s[b][j] + sigf(g0[0]) * tanhf(g0[2]);
        float h1 = sigf(g0[3]) * tanhf(c1);
        __syncthreads();
        h1s[b][j] = h1; c1s[b][j] = c1;
        __syncthreads();

        float g1[4];
#pragma unroll
        for (int g = 0; g < 4; g++) {
            int idx = g * 32 + j;
            float s = bih1[idx] + bhh1[idx];
            for (int k = 0; k < 32; k++)
                s += Wih1[idx * 32 + k] * h1s[b][k] + Whh1[idx * 32 + k] * h2s[b][k];
            g1[g] = s;
        }
        float c2 = sigf(g1[1]) * c2s[b][j] + sigf(g1[0]) * tanhf(g1[2]);
        float h2 = sigf(g1[3]) * tanhf(c2);
        __syncthreads();
        h2s[b][j] = h2; c2s[b][j] = c2;
        __syncthreads();
    }

    float s = ffb[j];
    for (int k = 0; k < 31; k++) s += tf[b * 31 + k] * ffW[j * 31 + k];
    feats[b][j] = fmaxf(s, 0.f);
    __syncthreads();

    if (tid < 64) {
        int bb = tid >> 1, f = tid & 1;
        float s2 = 0.f;
        for (int c = 0; c < 32; c++)
            s2 += h2s[bb][c] * gcnW[f * 80 + 16 + c] + feats[bb][c] * gcnW[f * 80 + 48 + c];
        d_scratch[OFF_TVF + bb * 2 + f] = s2;
    }
}

// GRU1 r/u gates: [A@x(2) | A@h1(16)] -> U, r1*h1 (bf16 transposed, cols 32..47)
__global__ __launch_bounds__(256) void gates1K(const float* __restrict__ rW, const float* __restrict__ rb,
                                               const float* __restrict__ uW, const float* __restrict__ ub,
                                               int g, int p) {
    int r = blockIdx.x * 256 + threadIdx.x;
    int b = r >> 10, n = r & 1023;
    const float* ax  = d_scratch + OFF_AX + (size_t)g * 524288 + (size_t)r * 16 + p * 2;
    const float* ah1 = d_scratch + OFF_Y32 + (size_t)r * 32;
    const float* h1  = d_scratch + OFF_H   + (size_t)r * 32;
    __nv_bfloat16* xo = d_xbf + ((size_t)b * 64 + 32) * NN + n;
    float xh[18];
    xh[0] = ax[0]; xh[1] = ax[1];
#pragma unroll
    for (int k = 0; k < 16; k++) xh[2 + k] = ah1[k];
#pragma unroll
    for (int j = 0; j < 16; j++) {
        float sr = rb[j], su = ub[j];
#pragma unroll
        for (int k = 0; k < 18; k++) { sr += xh[k] * rW[j * 18 + k]; su += xh[k] * uW[j * 18 + k]; }
        d_scratch[OFF_U + (size_t)r * 16 + j] = sigf(su);
        xo[(size_t)j * NN] = __float2bfloat16_rn(sigf(sr) * h1[j]);
    }
}

// GRU1 candidate + state update -> H (fp32) + xbf cols 0..15
__global__ __launch_bounds__(256) void gates2K(const float* __restrict__ cW, const float* __restrict__ cb,
                                               int g, int p) {
    int r = blockIdx.x * 256 + threadIdx.x;
    int b = r >> 10, n = r & 1023;
    const float* ax  = d_scratch + OFF_AX + (size_t)g * 524288 + (size_t)r * 16 + p * 2;
    const float* arh = d_scratch + OFF_ARH + (size_t)r * 16;
    const float* u   = d_scratch + OFF_U   + (size_t)r * 16;
    __nv_bfloat16* xo = d_xbf + (size_t)b * 64 * NN + n;
    float xh[18];
    xh[0] = ax[0]; xh[1] = ax[1];
#pragma unroll
    for (int k = 0; k < 16; k++) xh[2 + k] = arh[k];
#pragma unroll
    for (int j = 0; j < 16; j++) {
        float s = cb[j];
#pragma unroll
        for (int k = 0; k < 18; k++) s += xh[k] * cW[j * 18 + k];
        float c = tanhf(s);
        float h1 = d_scratch[OFF_H + (size_t)r * 32 + j];
        float hn = u[j] * h1 + (1.f - u[j]) * c;
        d_scratch[OFF_H + (size_t)r * 32 + j] = hn;
        xo[(size_t)j * NN] = __float2bfloat16_rn(hn);
    }
}

// GRU2 r/u gates: [A@h1'(16) | A@h2(16)] -> U, r2*h2 (cols 32..47)
__global__ __launch_bounds__(256) void gates3K(const float* __restrict__ rW, const float* __restrict__ rb,
                                               const float* __restrict__ uW, const float* __restrict__ ub) {
    int r = blockIdx.x * 256 + threadIdx.x;
    int b = r >> 10, n = r & 1023;
    const float* ax1 = d_scratch + OFF_AX1 + (size_t)r * 16;
    const float* ah2 = d_scratch + OFF_Y32 + (size_t)r * 32 + 16;
    const float* h2  = d_scratch + OFF_H   + (size_t)r * 32 + 16;
    __nv_bfloat16* xo = d_xbf + ((size_t)b * 64 + 32) * NN + n;
    float xh[32];
#pragma unroll
    for (int k = 0; k < 16; k++) { xh[k] = ax1[k]; xh[16 + k] = ah2[k]; }
#pragma unroll
    for (int j = 0; j < 16; j++) {
        float sr = rb[j], su = ub[j];
#pragma unroll
        for (int k = 0; k < 32; k++) { sr += xh[k] * rW[j * 32 + k]; su += xh[k] * uW[j * 32 + k]; }
        d_scratch[OFF_U + (size_t)r * 16 + j] = sigf(su);
        xo[(size_t)j * NN] = __float2bfloat16_rn(sigf(sr) * h2[j]);
    }
}

// GRU2 candidate + state update -> H (fp32) + xbf cols 16..31
__global__ __launch_bounds__(256) void gates4K(const float* __restrict__ cW, const float* __restrict__ cb) {
    int r = blockIdx.x * 256 + threadIdx.x;
    int b = r >> 10, n = r & 1023;
    const float* ax1 = d_scratch + OFF_AX1 + (size_t)r * 16;
    const float* arh = d_scratch + OFF_ARH + (size_t)r * 16;
    const float* u   = d_scratch + OFF_U   + (size_t)r * 16;
    __nv_bfloat16* xo = d_xbf + ((size_t)b * 64 + 16) * NN + n;
    float xh[32];
#pragma unroll
    for (int k = 0; k < 16; k++) { xh[k] = ax1[k]; xh[16 + k] = arh[k]; }
#pragma unroll
    for (int j = 0; j < 16; j++) {
        float s = cb[j];
#pragma unroll
        for (int k = 0; k < 32; k++) s += xh[k] * cW[j * 32 + k];
        float c = tanhf(s);
        float h2 = d_scratch[OFF_H + (size_t)r * 32 + 16 + j];
        float hn = u[j] * h2 + (1.f - u[j]) * c;
        d_scratch[OFF_H + (size_t)r * 32 + 16 + j] = hn;
        xo[(size_t)j * NN] = __float2bfloat16_rn(hn);
    }
}

// out[b,n,f] = tanh( (A@h2) . gcnW[f,0:16] + rowsum*tvf[b,f] + gcn_b[f] )
__global__ __launch_bounds__(256) void finalK(const float* __restrict__ gcnW,
                                              const float* __restrict__ gcnb,
                                              float* __restrict__ out) {
    int r = blockIdx.x * 256 + threadIdx.x;
    int b = r >> 10;
    const float* arec = d_scratch + OFF_ARH + (size_t)r * 16;
    float rs = d_scratch[OFF_RS + r];
#pragma unroll
    for (int f = 0; f < 2; f++) {
        float s = gcnb[f] + rs * d_scratch[OFF_TVF + b * 2 + f];
#pragma unroll
        for (int c = 0; c < 16; c++) s += arec[c] * gcnW[f * 80 + c];
        out[r * 2 + f] = tanhf(s);
    }
}

// ================================== launcher ===================================

extern "C" void kernel_launch(void* const* d_in, const int* in_sizes, int n_in,
                              void* d_out, int out_size) {
    const float* recent = (const float*)d_in[0];
    const float* trend  = (const float*)d_in[1];
    const float* A      = (const float*)d_in[2];
    const float* tf     = (const float*)d_in[3];
    const float* g1rW = (const float*)d_in[4],  *g1rb = (const float*)d_in[5];
    const float* g1uW = (const float*)d_in[6],  *g1ub = (const float*)d_in[7];
    const float* g1cW = (const float*)d_in[8],  *g1cb = (const float*)d_in[9];
    const float* g2rW = (const float*)d_in[10], *g2rb = (const float*)d_in[11];
    const float* g2uW = (const float*)d_in[12], *g2ub = (const float*)d_in[13];
    const float* g2cW = (const float*)d_in[14], *g2cb = (const float*)d_in[15];
    const float* Wih0 = (const float*)d_in[16], *Whh0 = (const float*)d_in[17];
    const float* bih0 = (const float*)d_in[18], *bhh0 = (const float*)d_in[19];
    const float* Wih1 = (const float*)d_in[20], *Whh1 = (const float*)d_in[21];
    const float* bih1 = (const float*)d_in[22], *bhh1 = (const float*)d_in[23];
    const float* ffW  = (const float*)d_in[24], *ffb  = (const float*)d_in[25];
    const float* gcnW = (const float*)d_in[26], *gcnb = (const float*)d_in[27];
    float* out = (float*)d_out;

    dim3 gg(8, 32);        // (N/128 row tiles, B)
    dim3 ge(128);          // elementwise grid: B*N / 256

    convAK<<<16384, 256>>>(A);
    zeroHK<<<4096, 256>>>();
    zeroXK<<<1024, 256>>>();
    prepK<<<1, 1024>>>(trend, tf, Wih0, Whh0, bih0, bhh0,
                       Wih1, Whh1, bih1, bhh1, ffW, ffb, gcnW);
    rowsumK<<<4096, 256>>>(A);

    // Hoisted A @ x_t for all 24 timesteps (3 groups of 8)
    for (int g = 0; g < 3; g++) {
        gatherK<<<ge, 256>>>(recent, g);
        gemmT<16><<<gg, 128>>>(48, OFF_AX + g * 524288);
    }

    for (int t = 0; t < TT; t++) {
        int g = t >> 3, p = t & 7;
        gemmT<32><<<gg, 128>>>(0, OFF_Y32);              // [A@h1 | A@h2]
        gates1K<<<ge, 256>>>(g1rW, g1rb, g1uW, g1ub, g, p);
        gemmT<16><<<gg, 128>>>(32, OFF_ARH);             // A@(r1*h1)
        gates2K<<<ge, 256>>>(g1cW, g1cb, g, p);
        gemmT<16><<<gg, 128>>>(0, OFF_AX1);              // A@h1'
        gates3K<<<ge, 256>>>(g2rW, g2rb, g2uW, g2ub);
        gemmT<16><<<gg, 128>>>(32, OFF_ARH);             // A@(r2*h2)
        gates4K<<<ge, 256>>>(g2cW, g2cb);
    }

    gemmT<16><<<gg, 128>>>(16, OFF_ARH);                 // A@h2 (recent part)
    finalK<<<ge, 256>>>(gcnW, gcnb, out);
}

// round 3
// speedup vs baseline: 2.2835x; 1.2348x over previous
#include <cuda_runtime.h>
#include <cuda_bf16.h>
#include <math.h>

#define BB 32
#define TT 24
#define NN 1024
#define KC 64
#define KT (NN / KC)
#define NCTA 128
#define NTHR 256

// ---------------- fp32 scratch ----------------
#define OFF_AX   0                          // 3 groups x (B,N,16) = A@x_t
#define OFF_RS   (3 * BB * NN * 16)         // (B,N) rowsum(A)
#define OFF_TVF  (OFF_RS + BB * NN)         // (B,2)
#define SCRATCH_FLOATS (OFF_TVF + BB * 2)

__device__ float d_scratch[SCRATCH_FLOATS];
__device__ __nv_bfloat16 d_Abf[(size_t)BB * NN * NN];     // A bf16 (L2-resident)
__device__ __nv_bfloat16 d_xbf[(size_t)BB * 48 * NN];     // X^T: 0-15 h1, 16-31 h2, 32-47 r*h
__device__ __nv_bfloat16 d_xt [(size_t)BB * 48 * NN];     // gathered x_t (24t x 2f), transposed
__device__ unsigned g_cnt = 0;
__device__ volatile unsigned g_gen = 0;

// smem word-offsets (dynamic smem, unsigned words)
#define SW_AS   0        // A tiles: 2 x 256 x 36
#define SW_XS   18432    // X tiles: 2 x 32 x 36
#define SW_W1RU 20736    // float2[16*18] (r,u) gru1
#define SW_W2RU 21312    // float2[16*32] (r,u) gru2
#define SW_W1CP 22336    // float2[18*8]  c gru1, (j,j+1) pairs, [k][m]
#define SW_W2CP 22624    // float2[32*8]  c gru2
#define SW_B1RU 23136
#define SW_B2RU 23168
#define SW_B1CP 23200
#define SW_B2CP 23216
#define SW_GCNW 23232    // float[32]  gcnW[f][0:16]
#define SW_GCNB 23264    // float[2]
#define SMEM_WORDS 23266
#define SMEM_BYTES (SMEM_WORDS * 4 + 8)

__device__ __forceinline__ float sigf(float x) { return 1.0f / (1.0f + expf(-x)); }

__device__ __forceinline__ void cpa16s(unsigned* sm, const void* gm) {
    unsigned sa = (unsigned)__cvta_generic_to_shared(sm);
    asm volatile("cp.async.cg.shared.global [%0], [%1], 16;" :: "r"(sa), "l"(gm) : "memory");
}
#define CP_COMMIT() asm volatile("cp.async.commit_group;" ::: "memory")
#define CP_WAIT(n)  asm volatile("cp.async.wait_group %0;" :: "n"(n) : "memory")

__device__ __forceinline__ unsigned long long dup2(float x) {
    unsigned long long r; unsigned u = __float_as_uint(x);
    asm("mov.b64 %0, {%1, %1};" : "=l"(r) : "r"(u));
    return r;
}
__device__ __forceinline__ void fma2(unsigned long long& s, unsigned long long a, unsigned long long w) {
    asm("fma.rn.f32x2 %0, %1, %2, %0;" : "+l"(s) : "l"(a), "l"(w));
}
__device__ __forceinline__ void unpack2(unsigned long long s, float& x, float& y) {
    unsigned lo, hi; asm("mov.b64 {%0, %1}, %2;" : "=r"(lo), "=r"(hi) : "l"(s));
    x = __uint_as_float(lo); y = __uint_as_float(hi);
}

__device__ __forceinline__ void gridbar() {
    __threadfence();
    __syncthreads();
    if (threadIdx.x == 0) {
        unsigned gen = g_gen;
        if (atomicAdd(&g_cnt, 1) == NCTA - 1) {
            g_cnt = 0;
            __threadfence();
            g_gen = gen + 1;
        } else {
            while (g_gen == gen) __nanosleep(64);
        }
        __threadfence();
    }
    __syncthreads();
}

// ---------- GEMM phase: acc[256 own rows x C] = A_own(256x1024) @ X^T(C x 1024)^T ----------
template <int C>
__device__ __forceinline__ void gemmP(const __nv_bfloat16* __restrict__ Ab,
                                      const __nv_bfloat16* __restrict__ Xb,
                                      unsigned* smem_u, float acc[2][C / 8][4]) {
    unsigned* As = smem_u + SW_AS;
    unsigned* Xs = smem_u + SW_XS;
    const int tid = threadIdx.x, w = tid >> 5, lane = tid & 31;
#pragma unroll
    for (int mt = 0; mt < 2; mt++)
#pragma unroll
        for (int nt = 0; nt < C / 8; nt++)
#pragma unroll
            for (int q = 0; q < 4; q++) acc[mt][nt][q] = 0.f;

    auto load = [&](int buf, int k0) {
        unsigned* Ad = As + buf * 9216;
#pragma unroll
        for (int i = 0; i < 8; i++) {
            int ch = tid + i * 256, r = ch >> 3, j = ch & 7;
            cpa16s(Ad + r * 36 + j * 4, Ab + (size_t)r * NN + k0 + j * 8);
        }
        unsigned* Xd = Xs + buf * 1152;
        if (C == 32) {
            int r = tid >> 3, j = tid & 7;
            cpa16s(Xd + r * 36 + j * 4, Xb + (size_t)r * NN + k0 + j * 8);
        } else if (tid < 128) {
            int r = tid >> 3, j = tid & 7;
            cpa16s(Xd + r * 36 + j * 4, Xb + (size_t)r * NN + k0 + j * 8);
        }
    };

    const unsigned aoff = ((unsigned)(w * 32 + (lane & 15)) * 36 + (lane >> 4) * 4) * 4;
    const unsigned boff = ((unsigned)(lane & 7) * 36 + ((lane >> 3) & 1) * 4) * 4;

    load(0, 0);
    CP_COMMIT();
    for (int kt = 0; kt < KT; kt++) {
        int cur = kt & 1;
        if (kt + 1 < KT) {
            load(cur ^ 1, (kt + 1) * KC);
            CP_COMMIT();
            CP_WAIT(1);
        } else {
            CP_WAIT(0);
        }
        __syncthreads();
        unsigned aB = (unsigned)__cvta_generic_to_shared(As + cur * 9216);
        unsigned xB = (unsigned)__cvta_generic_to_shared(Xs + cur * 1152);
#pragma unroll
        for (int ks = 0; ks < 4; ks++) {
            const unsigned kb = (unsigned)ks * 32;
            unsigned bf[C / 8][2];
#pragma unroll
            for (int nt = 0; nt < C / 8; nt++) {
                unsigned ad = xB + boff + (unsigned)nt * 8 * 36 * 4 + kb;
                asm volatile("ldmatrix.sync.aligned.m8n8.x2.shared.b16 {%0,%1}, [%2];"
                             : "=r"(bf[nt][0]), "=r"(bf[nt][1]) : "r"(ad));
            }
#pragma unroll
            for (int mt = 0; mt < 2; mt++) {
                unsigned a0, a1, a2, a3;
                unsigned ad = aB + aoff + (unsigned)mt * 16 * 36 * 4 + kb;
                asm volatile("ldmatrix.sync.aligned.m8n8.x4.shared.b16 {%0,%1,%2,%3}, [%4];"
                             : "=r"(a0), "=r"(a1), "=r"(a2), "=r"(a3) : "r"(ad));
#pragma unroll
                for (int nt = 0; nt < C / 8; nt++) {
                    asm volatile(
                        "mma.sync.aligned.m16n8k16.row.col.f32.bf16.bf16.f32 "
                        "{%0,%1,%2,%3},{%4,%5,%6,%7},{%8,%9},{%0,%1,%2,%3};"
                        : "+f"(acc[mt][nt][0]), "+f"(acc[mt][nt][1]),
                          "+f"(acc[mt][nt][2]), "+f"(acc[mt][nt][3])
                        : "r"(a0), "r"(a1), "r"(a2), "r"(a3),
                          "r"(bf[nt][0]), "r"(bf[nt][1]));
                }
            }
        }
        __syncthreads();
    }
}

// write acc fragments to smem stage (row-major, pitch 33) so each thread can read its row
template <int C>
__device__ __forceinline__ void stageStore(float* stage, const float acc[2][C / 8][4]) {
    const int lane = threadIdx.x & 31, w = threadIdx.x >> 5;
    const int g = lane >> 2, c2 = (lane & 3) * 2;
#pragma unroll
    for (int mt = 0; mt < 2; mt++) {
        int rr = w * 32 + mt * 16 + g;
#pragma unroll
        for (int nt = 0; nt < C / 8; nt++) {
            int col = nt * 8 + c2;
            stage[rr * 33 + col]       = acc[mt][nt][0];
            stage[rr * 33 + col + 1]   = acc[mt][nt][1];
            stage[(rr + 8) * 33 + col]     = acc[mt][nt][2];
            stage[(rr + 8) * 33 + col + 1] = acc[mt][nt][3];
        }
    }
}

// ================= persistent kernel: whole GCGRU + final GCN =================
__global__ void __launch_bounds__(NTHR, 1) persistK(
    const float* __restrict__ A, const float* __restrict__ recent,
    const float* __restrict__ g1rW, const float* __restrict__ g1rb,
    const float* __restrict__ g1uW, const float* __restrict__ g1ub,
    const float* __restrict__ g1cW, const float* __restrict__ g1cb,
    const float* __restrict__ g2rW, const float* __restrict__ g2rb,
    const float* __restrict__ g2uW, const float* __restrict__ g2ub,
    const float* __restrict__ g2cW, const float* __restrict__ g2cb,
    const float* __restrict__ gcnW, const float* __restrict__ gcnb,
    float* __restrict__ out) {
    extern __shared__ unsigned smem_u[];
    float* stage = (float*)smem_u;

    const int tid = threadIdx.x, w = tid >> 5, lane = tid & 31;
    const int b = blockIdx.x >> 2, rb = blockIdx.x & 3;
    const int row0 = rb * 256, n0 = row0 + tid;
    const size_t r0 = (size_t)b * NN + n0;

    // ---- weight tables into smem ----
    {
        float2* W1 = (float2*)(smem_u + SW_W1RU);
        for (int i = tid; i < 288; i += NTHR) W1[i] = make_float2(g1rW[i], g1uW[i]);
        float2* W2 = (float2*)(smem_u + SW_W2RU);
        for (int i = tid; i < 512; i += NTHR) W2[i] = make_float2(g2rW[i], g2uW[i]);
        float2* C1 = (float2*)(smem_u + SW_W1CP);
        for (int i = tid; i < 144; i += NTHR) {
            int k = i >> 3, m = i & 7;
            C1[i] = make_float2(g1cW[(2 * m) * 18 + k], g1cW[(2 * m + 1) * 18 + k]);
        }
        float2* C2 = (float2*)(smem_u + SW_W2CP);
        for (int i = tid; i < 256; i += NTHR) {
            int k = i >> 3, m = i & 7;
            C2[i] = make_float2(g2cW[(2 * m) * 32 + k], g2cW[(2 * m + 1) * 32 + k]);
        }
        if (tid < 16) ((float2*)(smem_u + SW_B1RU))[tid] = make_float2(g1rb[tid], g1ub[tid]);
        else if (tid < 32) ((float2*)(smem_u + SW_B2RU))[tid - 16] = make_float2(g2rb[tid - 16], g2ub[tid - 16]);
        else if (tid < 40) ((float2*)(smem_u + SW_B1CP))[tid - 32] = make_float2(g1cb[2 * (tid - 32)], g1cb[2 * (tid - 32) + 1]);
        else if (tid < 48) ((float2*)(smem_u + SW_B2CP))[tid - 40] = make_float2(g2cb[2 * (tid - 40)], g2cb[2 * (tid - 40) + 1]);
        else if (tid < 80) { int i = tid - 48; ((float*)(smem_u + SW_GCNW))[i] = gcnW[(i >> 4) * 80 + (i & 15)]; }
        else if (tid < 82) ((float*)(smem_u + SW_GCNB))[tid - 80] = gcnb[tid - 80];
    }

    // ---- convert own A slice to bf16 + exact fp32 rowsum ----
    const float* Arow = A + ((size_t)b * NN + row0) * NN;
    __nv_bfloat16* Abrow = d_Abf + ((size_t)b * NN + row0) * NN;
    for (int i = tid; i < 256 * NN / 8; i += NTHR) {
        size_t o = (size_t)i * 8;
        float4 v0 = *(const float4*)(Arow + o);
        float4 v1 = *(const float4*)(Arow + o + 4);
        __nv_bfloat162 b0 = __float22bfloat162_rn(make_float2(v0.x, v0.y));
        __nv_bfloat162 b1 = __float22bfloat162_rn(make_float2(v0.z, v0.w));
        __nv_bfloat162 b2 = __float22bfloat162_rn(make_float2(v1.x, v1.y));
        __nv_bfloat162 b3 = __float22bfloat162_rn(make_float2(v1.z, v1.w));
        uint4 u;
        u.x = *(unsigned*)&b0; u.y = *(unsigned*)&b1; u.z = *(unsigned*)&b2; u.w = *(unsigned*)&b3;
        *(uint4*)(Abrow + o) = u;
    }
    for (int i = 0; i < 32; i++) {
        int rr = w * 32 + i;
        const float4* ap = (const float4*)(Arow + (size_t)rr * NN);
        float s = 0.f;
#pragma unroll 4
        for (int q = lane; q < 256; q += 32) {
            float4 v = ap[q];
            s += (v.x + v.y) + (v.z + v.w);
        }
#pragma unroll
        for (int o = 16; o; o >>= 1) s += __shfl_xor_sync(~0u, s, o);
        if (!lane) d_scratch[OFF_RS + (size_t)b * NN + row0 + rr] = s;
    }

    // ---- gather x_t (transposed bf16) + zero h columns ----
    {
        const float2* rp = (const float2*)recent;
        for (int t = 0; t < TT; t++) {
            float2 v = rp[(size_t)(b * TT + t) * NN + n0];
            d_xt[((size_t)b * 48 + 2 * t) * NN + n0]     = __float2bfloat16_rn(v.x);
            d_xt[((size_t)b * 48 + 2 * t + 1) * NN + n0] = __float2bfloat16_rn(v.y);
        }
        __nv_bfloat16 z = __float2bfloat16_rn(0.f);
        for (int c = 0; c < 32; c++) d_xbf[((size_t)b * 48 + c) * NN + n0] = z;
    }

    float h1[16], h2[16], uu[16], ah2s[16], ah1p[16];
#pragma unroll
    for (int k = 0; k < 16; k++) { h1[k] = 0.f; h2[k] = 0.f; }

    gridbar();   // d_xt, d_xbf zeros, d_Abf visible everywhere

    // ---- A @ x_t for all 24 timesteps (outputs are CTA-local; no barrier) ----
    for (int g = 0; g < 3; g++) {
        float a16[2][2][4];
        gemmP<16>(Abrow, d_xt + ((size_t)b * 48 + g * 16) * NN, smem_u, a16);
        stageStore<16>(stage, a16);
        __syncthreads();
        float* axp = d_scratch + OFF_AX + (size_t)g * (BB * NN * 16) + r0 * 16;
        const float* srow = stage + tid * 33;
#pragma unroll
        for (int q = 0; q < 4; q++)
            ((float4*)axp)[q] = make_float4(srow[4 * q], srow[4 * q + 1], srow[4 * q + 2], srow[4 * q + 3]);
        __syncthreads();
    }

    const __nv_bfloat16* xbB = d_xbf + (size_t)b * 48 * NN;
    __nv_bfloat16* xo_h1 = d_xbf + ((size_t)b * 48 + 0) * NN + n0;
    __nv_bfloat16* xo_h2 = d_xbf + ((size_t)b * 48 + 16) * NN + n0;
    __nv_bfloat16* xo_rh = d_xbf + ((size_t)b * 48 + 32) * NN + n0;

    const unsigned long long* W1ru = (const unsigned long long*)(smem_u + SW_W1RU);
    const unsigned long long* W2ru = (const unsigned long long*)(smem_u + SW_W2RU);
    const unsigned long long* W1cp = (const unsigned long long*)(smem_u + SW_W1CP);
    const unsigned long long* W2cp = (const unsigned long long*)(smem_u + SW_W2CP);
    const unsigned long long* B1ru = (const unsigned long long*)(smem_u + SW_B1RU);
    const unsigned long long* B2ru = (const unsigned long long*)(smem_u + SW_B2RU);
    const unsigned long long* B1cp = (const unsigned long long*)(smem_u + SW_B1CP);
    const unsigned long long* B2cp = (const unsigned long long*)(smem_u + SW_B2CP);

    for (int t = 0; t < TT; t++) {
        const int g = t >> 3, p = t & 7;
        const float* axp = d_scratch + OFF_AX + (size_t)g * (BB * NN * 16) + r0 * 16 + p * 2;

        // ---- phase 1: [A@h1 | A@h2], gates1 ----
        {
            float a32[2][4][4];
            gemmP<32>(Abrow, xbB, smem_u, a32);
            stageStore<32>(stage, a32);
            __syncthreads();
            const float* srow = stage + tid * 33;
            float2 axv = *(const float2*)axp;
            float xh[18];
            xh[0] = axv.x; xh[1] = axv.y;
#pragma unroll
            for (int k = 0; k < 16; k++) { xh[2 + k] = srow[k]; ah2s[k] = srow[16 + k]; }
#pragma unroll
            for (int j = 0; j < 16; j++) {
                unsigned long long s = B1ru[j];
#pragma unroll
                for (int k = 0; k < 18; k++) fma2(s, dup2(xh[k]), W1ru[j * 18 + k]);
                float sr, su; unpack2(s, sr, su);
                uu[j] = sigf(su);
                xo_rh[(size_t)j * NN] = __float2bfloat16_rn(sigf(sr) * h1[j]);
            }
            __syncthreads();
        }
        gridbar();

        // ---- phase 2: A@(r1*h1), gates2 -> h1' ----
        {
            float a16[2][2][4];
            gemmP<16>(Abrow, xbB + (size_t)32 * NN, smem_u, a16);
            stageStore<16>(stage, a16);
            __syncthreads();
            const float* srow = stage + tid * 33;
            float2 axv = *(const float2*)axp;
            float xh[18];
            xh[0] = axv.x; xh[1] = axv.y;
#pragma unroll
            for (int k = 0; k < 16; k++) xh[2 + k] = srow[k];
            unsigned long long sm[8];
#pragma unroll
            for (int m = 0; m < 8; m++) sm[m] = B1cp[m];
#pragma unroll
            for (int k = 0; k < 18; k++) {
                unsigned long long a = dup2(xh[k]);
#pragma unroll
                for (int m = 0; m < 8; m++) fma2(sm[m], a, W1cp[k * 8 + m]);
            }
#pragma unroll
            for (int m = 0; m < 8; m++) {
                float c0, c1; unpack2(sm[m], c0, c1);
                int j = 2 * m;
                h1[j]     = uu[j]     * h1[j]     + (1.f - uu[j])     * tanhf(c0);
                h1[j + 1] = uu[j + 1] * h1[j + 1] + (1.f - uu[j + 1]) * tanhf(c1);
                xo_h1[(size_t)j * NN]       = __float2bfloat16_rn(h1[j]);
                xo_h1[(size_t)(j + 1) * NN] = __float2bfloat16_rn(h1[j + 1]);
            }
            __syncthreads();
        }
        gridbar();

        // ---- phase 3: A@h1', gates3 ----
        {
            float a16[2][2][4];
            gemmP<16>(Abrow, xbB, smem_u, a16);
            stageStore<16>(stage, a16);
            __syncthreads();
            const float* srow = stage + tid * 33;
#pragma unroll
            for (int k = 0; k < 16; k++) ah1p[k] = srow[k];
#pragma unroll
            for (int j = 0; j < 16; j++) {
                unsigned long long s = B2ru[j];
#pragma unroll
                for (int k = 0; k < 16; k++) fma2(s, dup2(ah1p[k]), W2ru[j * 32 + k]);
#pragma unroll
                for (int k = 0; k < 16; k++) fma2(s, dup2(ah2s[k]), W2ru[j * 32 + 16 + k]);
                float sr, su; unpack2(s, sr, su);
                uu[j] = sigf(su);
                xo_rh[(size_t)j * NN] = __float2bfloat16_rn(sigf(sr) * h2[j]);
            }
            __syncthreads();
        }
        gridbar();

        // ---- phase 4: A@(r2*h2), gates4 -> h2' ----
        {
            float a16[2][2][4];
            gemmP<16>(Abrow, xbB + (size_t)32 * NN, smem_u, a16);
            stageStore<16>(stage, a16);
            __syncthreads();
            const float* srow = stage + tid * 33;
            unsigned long long sm[8];
#pragma unroll
            for (int m = 0; m < 8; m++) sm[m] = B2cp[m];
#pragma unroll
            for (int k = 0; k < 16; k++) {
                unsigned long long a = dup2(ah1p[k]);
#pragma unroll
                for (int m = 0; m < 8; m++) fma2(sm[m], a, W2cp[k * 8 + m]);
            }
#pragma unroll
            for (int k = 0; k < 16; k++) {
                unsigned long long a = dup2(srow[k]);
#pragma unroll
                for (int m = 0; m < 8; m++) fma2(sm[m], a, W2cp[(16 + k) * 8 + m]);
            }
#pragma unroll
            for (int m = 0; m < 8; m++) {
                float c0, c1; unpack2(sm[m], c0, c1);
                int j = 2 * m;
                h2[j]     = uu[j]     * h2[j]     + (1.f - uu[j])     * tanhf(c0);
                h2[j + 1] = uu[j + 1] * h2[j + 1] + (1.f - uu[j + 1]) * tanhf(c1);
                xo_h2[(size_t)j * NN]       = __float2bfloat16_rn(h2[j]);
                xo_h2[(size_t)(j + 1) * NN] = __float2bfloat16_rn(h2[j + 1]);
            }
            __syncthreads();
        }
        gridbar();
    }

    // ---- final: A@h2 + folded trend/feat, tanh, write output ----
    {
        float a16[2][2][4];
        gemmP<16>(Abrow, xbB + (size_t)16 * NN, smem_u, a16);
        stageStore<16>(stage, a16);
        __syncthreads();
        const float* srow = stage + tid * 33;
        const float* gw = (const float*)(smem_u + SW_GCNW);
        const float* gb = (const float*)(smem_u + SW_GCNB);
        float rs = d_scratch[OFF_RS + r0];
        float o0 = gb[0] + rs * d_scratch[OFF_TVF + b * 2];
        float o1 = gb[1] + rs * d_scratch[OFF_TVF + b * 2 + 1];
#pragma unroll
        for (int c = 0; c < 16; c++) {
            o0 += srow[c] * gw[c];
            o1 += srow[c] * gw[16 + c];
        }
        *(float2*)(out + r0 * 2) = make_float2(tanhf(o0), tanhf(o1));
    }
}

// ---- 2-layer LSTM + feat FF folded into tvf (B,2); tiny, one block ----
__global__ __launch_bounds__(1024) void prepK(
    const float* __restrict__ trend, const float* __restrict__ tf,
    const float* __restrict__ Wih0, const float* __restrict__ Whh0,
    const float* __restrict__ bih0, const float* __restrict__ bhh0,
    const float* __restrict__ Wih1, const float* __restrict__ Whh1,
    const float* __restrict__ bih1, const float* __restrict__ bhh1,
    const float* __restrict__ ffW, const float* __restrict__ ffb,
    const float* __restrict__ gcnW) {
    __shared__ float h1s[32][32], c1s[32][32], h2s[32][32], c2s[32][32], feats[32][32];
    int tid = threadIdx.x;
    int b = tid >> 5, j = tid & 31;
    h1s[b][j] = 0.f; c1s[b][j] = 0.f; h2s[b][j] = 0.f; c2s[b][j] = 0.f;
    __syncthreads();

    for (int t = 0; t < TT; t++) {
        float x0 = trend[(b * TT + t) * 2 + 0];
        float x1 = trend[(b * TT + t) * 2 + 1];
        float g0[4];
#pragma unroll
        for (int g = 0; g < 4; g++) {
            int idx = g * 32 + j;
            float s = bih0[idx] + bhh0[idx] + Wih0[idx * 2] * x0 + Wih0[idx * 2 + 1] * x1;
            for (int k = 0; k < 32; k++) s += Whh0[idx * 32 + k] * h1s[b][k];
            g0[g] = s;
        }
        float c1 = sigf(g0[1]) * c1s[b][j] + sigf(g0[0]) * tanhf(g0[2]);
        float h1 = sigf(g0[3]) * tanhf(c1);
        __syncthreads();
        h1s[b][j] = h1; c1s[b][j] = c1;
        __syncthreads();

        float g1[4];
#pragma unroll
        for (int g = 0; g < 4; g++) {
            int idx = g * 32 + j;
            float s = bih1[idx] + bhh1[idx];
            for (int k = 0; k < 32; k++)
                s += Wih1[idx * 32 + k] * h1s[b][k] + Whh1[idx * 32 + k] * h2s[b][k];
            g1[g] = s;
        }
        float c2 = sigf(g1[1]) * c2s[b][j] + sigf(g1[0]) * tanhf(g1[2]);
        float h2 = sigf(g1[3]) * tanhf(c2);
        __syncthreads();
        h2s[b][j] = h2; c2s[b][j] = c2;
        __syncthreads();
    }

    float s = ffb[j];
    for (int k = 0; k < 31; k++) s += tf[b * 31 + k] * ffW[j * 31 + k];
    feats[b][j] = fmaxf(s, 0.f);
    __syncthreads();

    if (tid < 64) {
        int bb = tid >> 1, f = tid & 1;
        float s2 = 0.f;
        for (int c = 0; c < 32; c++)
            s2 += h2s[bb][c] * gcnW[f * 80 + 16 + c] + feats[bb][c] * gcnW[f * 80 + 48 + c];
        d_scratch[OFF_TVF + bb * 2 + f] = s2;
    }
}

// ================================== launcher ===================================
extern "C" void kernel_launch(void* const* d_in, const int* in_sizes, int n_in,
                              void* d_out, int out_size) {
    const float* recent = (const float*)d_in[0];
    const float* trend  = (const float*)d_in[1];
    const float* A      = (const float*)d_in[2];
    const float* tf     = (const float*)d_in[3];
    const float* g1rW = (const float*)d_in[4],  *g1rb = (const float*)d_in[5];
    const float* g1uW = (const float*)d_in[6],  *g1ub = (const float*)d_in[7];
    const float* g1cW = (const float*)d_in[8],  *g1cb = (const float*)d_in[9];
    const float* g2rW = (const float*)d_in[10], *g2rb = (const float*)d_in[11];
    const float* g2uW = (const float*)d_in[12], *g2ub = (const float*)d_in[13];
    const float* g2cW = (const float*)d_in[14], *g2cb = (const float*)d_in[15];
    const float* Wih0 = (const float*)d_in[16], *Whh0 = (const float*)d_in[17];
    const float* bih0 = (const float*)d_in[18], *bhh0 = (const float*)d_in[19];
    const float* Wih1 = (const float*)d_in[20], *Whh1 = (const float*)d_in[21];
    const float* bih1 = (const float*)d_in[22], *bhh1 = (const float*)d_in[23];
    const float* ffW  = (const float*)d_in[24], *ffb  = (const float*)d_in[25];
    const float* gcnW = (const float*)d_in[26], *gcnb = (const float*)d_in[27];
    float* out = (float*)d_out;

    cudaFuncSetAttribute(persistK, cudaFuncAttributeMaxDynamicSharedMemorySize, SMEM_BYTES);

    prepK<<<1, 1024>>>(trend, tf, Wih0, Whh0, bih0, bhh0,
                       Wih1, Whh1, bih1, bhh1, ffW, ffb, gcnW);
    persistK<<<NCTA, NTHR, SMEM_BYTES>>>(A, recent,
                                         g1rW, g1rb, g1uW, g1ub, g1cW, g1cb,
                                         g2rW, g2rb, g2uW, g2ub, g2cW, g2cb,
                                         gcnW, gcnb, out);
}

// round 4
// speedup vs baseline: 2.5379x; 1.1114x over previous
#include <cuda_runtime.h>
#include <cuda_bf16.h>
#include <math.h>

#define BB 32
#define TT 24
#define NN 1024
#define KC 128
#define KT2 (NN / KC)          // 8 tiles
#define XP 68                  // X smem pitch in words (256B data + 16B pad)
#define NCTA 128
#define NTHR 256

// ---------------- fp32 scratch ----------------
#define OFF_AX   0                          // 3 groups x (B,N,16) = A@x_t
#define OFF_RS   (3 * BB * NN * 16)         // (B,N) rowsum(A)
#define OFF_TVF  (OFF_RS + BB * NN)         // (B,2)
#define SCRATCH_FLOATS (OFF_TVF + BB * 2)

__device__ float d_scratch[SCRATCH_FLOATS];
// A bf16, tile-major packed + swizzled: per CTA slice 8 tiles x 64KB contiguous
__device__ __nv_bfloat16 d_Apk[(size_t)BB * NN * NN];
__device__ __nv_bfloat16 d_xbf[(size_t)BB * 48 * NN];     // X^T: 0-15 h1, 16-31 h2, 32-47 r*h
__device__ __nv_bfloat16 d_xt [(size_t)BB * 48 * NN];     // gathered x_t, transposed
__device__ unsigned g_cnt = 0;
__device__ volatile unsigned g_gen = 0;

// smem word-offsets (dynamic)
#define SW_AS   0        // A tiles: 2 x 16384 words (64KB each)
#define SW_XS   32768    // X tiles: 2 x 32 x 68 words
#define SW_MB   37120    // 2 mbarriers
#define SW_W1RU 37128
#define SW_W2RU 37704
#define SW_W1CP 38728
#define SW_W2CP 39016
#define SW_B1RU 39528
#define SW_B2RU 39560
#define SW_B1CP 39592
#define SW_B2CP 39608
#define SW_GCNW 39624
#define SW_GCNB 39656
#define SMEM_WORDS 39658
#define SMEM_BYTES (SMEM_WORDS * 4 + 8)

__device__ __forceinline__ float sigf(float x) { return 1.0f / (1.0f + expf(-x)); }

__device__ __forceinline__ void cpa16s(unsigned* sm, const void* gm) {
    unsigned sa = (unsigned)__cvta_generic_to_shared(sm);
    asm volatile("cp.async.cg.shared.global [%0], [%1], 16;" :: "r"(sa), "l"(gm) : "memory");
}
#define CP_COMMIT() asm volatile("cp.async.commit_group;" ::: "memory")
#define CP_WAIT(n)  asm volatile("cp.async.wait_group %0;" :: "n"(n) : "memory")

__device__ __forceinline__ unsigned long long dup2(float x) {
    unsigned long long r; unsigned u = __float_as_uint(x);
    asm("mov.b64 %0, {%1, %1};" : "=l"(r) : "r"(u));
    return r;
}
__device__ __forceinline__ void fma2(unsigned long long& s, unsigned long long a, unsigned long long w) {
    asm("fma.rn.f32x2 %0, %1, %2, %0;" : "+l"(s) : "l"(a), "l"(w));
}
__device__ __forceinline__ void unpack2(unsigned long long s, float& x, float& y) {
    unsigned lo, hi; asm("mov.b64 {%0, %1}, %2;" : "=r"(lo), "=r"(hi) : "l"(s));
    x = __uint_as_float(lo); y = __uint_as_float(hi);
}

__device__ __forceinline__ void mbwait(unsigned mb, int phase) {
    asm volatile(
        "{\n\t.reg .pred P;\n\t"
        "W_%=:\n\t"
        "mbarrier.try_wait.parity.acquire.cta.shared::cta.b64 P, [%0], %1, 0x989680;\n\t"
        "@P bra.uni D_%=;\n\t"
        "bra.uni W_%=;\n\t"
        "D_%=:\n\t}"
        :: "r"(mb), "r"((unsigned)phase) : "memory");
}

__device__ __forceinline__ void gridbar() {
    __threadfence();
    __syncthreads();
    if (threadIdx.x == 0) {
        unsigned gen = g_gen;
        if (atomicAdd(&g_cnt, 1) == NCTA - 1) {
            g_cnt = 0;
            __threadfence();
            g_gen = gen + 1;
        } else {
            while (g_gen == gen) __nanosleep(32);
        }
        __threadfence();
    }
    __syncthreads();
}

// ---------- GEMM phase: acc[256 own rows x C] = A_own(256x1024) @ X^T(C x 1024)^T ----------
// A tiles arrive via cp.async.bulk (64KB, mbarrier), X tiles via cp.async.
template <int C>
__device__ __forceinline__ void gemmP(const __nv_bfloat16* __restrict__ Apk,
                                      const __nv_bfloat16* __restrict__ Xb,
                                      unsigned* smem_u, float acc[2][C / 8][4]) {
    const int tid = threadIdx.x, w = tid >> 5, lane = tid & 31;
    const unsigned aB  = (unsigned)__cvta_generic_to_shared(smem_u + SW_AS);
    const unsigned mb0 = (unsigned)__cvta_generic_to_shared(smem_u + SW_MB);

#pragma unroll
    for (int mt = 0; mt < 2; mt++)
#pragma unroll
        for (int nt = 0; nt < C / 8; nt++)
#pragma unroll
            for (int q = 0; q < 4; q++) acc[mt][nt][q] = 0.f;

    auto issueA = [&](int buf, int kt) {
        if (tid == 0) {
            unsigned mb = mb0 + buf * 8;
            asm volatile("mbarrier.arrive.expect_tx.shared.b64 _, [%0], %1;"
                         :: "r"(mb), "r"(65536u) : "memory");
            unsigned dst = aB + buf * 65536;
            asm volatile("cp.async.bulk.shared::cluster.global.mbarrier::complete_tx::bytes "
                         "[%0], [%1], %2, [%3];"
                         :: "r"(dst), "l"(Apk + (size_t)kt * 32768), "r"(65536u), "r"(mb)
                         : "memory");
        }
    };
    auto issueX = [&](int buf, int kt) {
        unsigned* Xd = smem_u + SW_XS + buf * 2176;
#pragma unroll
        for (int q = 0; q < C / 16; q++) {
            int i = tid + q * 256;
            int c = i >> 4, ch = i & 15;
            cpa16s(Xd + c * XP + ch * 4, Xb + (size_t)c * NN + kt * 128 + ch * 8);
        }
        CP_COMMIT();
    };

    issueA(0, 0); issueA(1, 1);
    issueX(0, 0); issueX(1, 1);

    int ph0 = 0, ph1 = 0;
    const unsigned boff = ((unsigned)(lane & 7) * XP + ((lane >> 3) & 1) * 4) * 4;

    for (int kt = 0; kt < KT2; kt++) {
        const int cur = kt & 1;
        if (kt < KT2 - 1) { CP_WAIT(1); } else { CP_WAIT(0); }
        if (cur == 0) { mbwait(mb0, ph0); ph0 ^= 1; }
        else          { mbwait(mb0 + 8, ph1); ph1 ^= 1; }

        const unsigned aBase = aB + cur * 65536;
        const unsigned xB = (unsigned)__cvta_generic_to_shared(smem_u + SW_XS + cur * 2176);
#pragma unroll
        for (int ks = 0; ks < 8; ks++) {
            unsigned bf[C / 8][2];
#pragma unroll
            for (int nt = 0; nt < C / 8; nt++) {
                unsigned ad = xB + boff + (unsigned)nt * 8 * XP * 4 + (unsigned)ks * 32;
                asm volatile("ldmatrix.sync.aligned.m8n8.x2.shared.b16 {%0,%1}, [%2];"
                             : "=r"(bf[nt][0]), "=r"(bf[nt][1]) : "r"(ad));
            }
#pragma unroll
            for (int mt = 0; mt < 2; mt++) {
                const int r = w * 32 + mt * 16 + (lane & 15);
                const int ci = ks * 2 + (lane >> 4);
                const int phys = (ci & 8) | ((ci ^ r) & 7);
                unsigned a0, a1, a2, a3;
                unsigned ad = aBase + (unsigned)r * 256 + (unsigned)phys * 16;
                asm volatile("ldmatrix.sync.aligned.m8n8.x4.shared.b16 {%0,%1,%2,%3}, [%4];"
                             : "=r"(a0), "=r"(a1), "=r"(a2), "=r"(a3) : "r"(ad));
#pragma unroll
                for (int nt = 0; nt < C / 8; nt++) {
                    asm volatile(
                        "mma.sync.aligned.m16n8k16.row.col.f32.bf16.bf16.f32 "
                        "{%0,%1,%2,%3},{%4,%5,%6,%7},{%8,%9},{%0,%1,%2,%3};"
                        : "+f"(acc[mt][nt][0]), "+f"(acc[mt][nt][1]),
                          "+f"(acc[mt][nt][2]), "+f"(acc[mt][nt][3])
                        : "r"(a0), "r"(a1), "r"(a2), "r"(a3),
                          "r"(bf[nt][0]), "r"(bf[nt][1]));
                }
            }
        }
        __syncthreads();           // all reads of both smem buffers done before refill
        if (kt + 2 < KT2) { issueA(cur, kt + 2); issueX(cur, kt + 2); }
    }
}

// write acc fragments to smem stage (row-major, pitch 33)
template <int C>
__device__ __forceinline__ void stageStore(float* stage, const float acc[2][C / 8][4]) {
    const int lane = threadIdx.x & 31, w = threadIdx.x >> 5;
    const int g = lane >> 2, c2 = (lane & 3) * 2;
#pragma unroll
    for (int mt = 0; mt < 2; mt++) {
        int rr = w * 32 + mt * 16 + g;
#pragma unroll
        for (int nt = 0; nt < C / 8; nt++) {
            int col = nt * 8 + c2;
            stage[rr * 33 + col]           = acc[mt][nt][0];
            stage[rr * 33 + col + 1]       = acc[mt][nt][1];
            stage[(rr + 8) * 33 + col]     = acc[mt][nt][2];
            stage[(rr + 8) * 33 + col + 1] = acc[mt][nt][3];
        }
    }
}

// ================= persistent kernel =================
__global__ void __launch_bounds__(NTHR, 1) persistK(
    const float* __restrict__ A, const float* __restrict__ recent,
    const float* __restrict__ g1rW, const float* __restrict__ g1rb,
    const float* __restrict__ g1uW, const float* __restrict__ g1ub,
    const float* __restrict__ g1cW, const float* __restrict__ g1cb,
    const float* __restrict__ g2rW, const float* __restrict__ g2rb,
    const float* __restrict__ g2uW, const float* __restrict__ g2ub,
    const float* __restrict__ g2cW, const float* __restrict__ g2cb,
    const float* __restrict__ gcnW, const float* __restrict__ gcnb,
    float* __restrict__ out) {
    extern __shared__ unsigned smem_u[];
    float* stage = (float*)smem_u;

    const int tid = threadIdx.x, w = tid >> 5, lane = tid & 31;
    const int b = blockIdx.x >> 2, rb = blockIdx.x & 3;
    const int row0 = rb * 256, n0 = row0 + tid;
    const size_t r0 = (size_t)b * NN + n0;

    if (tid == 0) {
        unsigned mb = (unsigned)__cvta_generic_to_shared(smem_u + SW_MB);
        asm volatile("mbarrier.init.shared.b64 [%0], %1;" :: "r"(mb), "r"(1u) : "memory");
        asm volatile("mbarrier.init.shared.b64 [%0], %1;" :: "r"(mb + 8), "r"(1u) : "memory");
    }

    // ---- weight tables into smem ----
    {
        float2* W1 = (float2*)(smem_u + SW_W1RU);
        for (int i = tid; i < 288; i += NTHR) W1[i] = make_float2(g1rW[i], g1uW[i]);
        float2* W2 = (float2*)(smem_u + SW_W2RU);
        for (int i = tid; i < 512; i += NTHR) W2[i] = make_float2(g2rW[i], g2uW[i]);
        float2* C1 = (float2*)(smem_u + SW_W1CP);
        for (int i = tid; i < 144; i += NTHR) {
            int k = i >> 3, m = i & 7;
            C1[i] = make_float2(g1cW[(2 * m) * 18 + k], g1cW[(2 * m + 1) * 18 + k]);
        }
        float2* C2 = (float2*)(smem_u + SW_W2CP);
        for (int i = tid; i < 256; i += NTHR) {
            int k = i >> 3, m = i & 7;
            C2[i] = make_float2(g2cW[(2 * m) * 32 + k], g2cW[(2 * m + 1) * 32 + k]);
        }
        if (tid < 16) ((float2*)(smem_u + SW_B1RU))[tid] = make_float2(g1rb[tid], g1ub[tid]);
        else if (tid < 32) ((float2*)(smem_u + SW_B2RU))[tid - 16] = make_float2(g2rb[tid - 16], g2ub[tid - 16]);
        else if (tid < 40) ((float2*)(smem_u + SW_B1CP))[tid - 32] = make_float2(g1cb[2 * (tid - 32)], g1cb[2 * (tid - 32) + 1]);
        else if (tid < 48) ((float2*)(smem_u + SW_B2CP))[tid - 40] = make_float2(g2cb[2 * (tid - 40)], g2cb[2 * (tid - 40) + 1]);
        else if (tid < 80) { int i = tid - 48; ((float*)(smem_u + SW_GCNW))[i] = gcnW[(i >> 4) * 80 + (i & 15)]; }
        else if (tid < 82) ((float*)(smem_u + SW_GCNB))[tid - 80] = gcnb[tid - 80];
    }

    // ---- pack own A slice: fp32 -> bf16, tile-major, swizzled; fused exact rowsum ----
    const float* Arow = A + ((size_t)b * NN + row0) * NN;
    __nv_bfloat16* pk = d_Apk + (size_t)blockIdx.x * (256 * NN);
    for (int j = 0; j < 32; j++) {
        const int r = w * 32 + j;
        const float* srcr = Arow + (size_t)r * NN;
        __nv_bfloat16* dstr = pk + r * 128;     // + tile*32768 + phys*8
        float s = 0.f;
#pragma unroll
        for (int q = 0; q < 4; q++) {
            int ci = lane + q * 32;             // chunk index 0..127 over the row
            int tile = ci >> 4, ch = ci & 15;
            const float* sp = srcr + ci * 8;
            float4 v0 = *(const float4*)sp;
            float4 v1 = *(const float4*)(sp + 4);
            s += (v0.x + v0.y) + (v0.z + v0.w) + (v1.x + v1.y) + (v1.z + v1.w);
            __nv_bfloat162 b0 = __float22bfloat162_rn(make_float2(v0.x, v0.y));
            __nv_bfloat162 b1 = __float22bfloat162_rn(make_float2(v0.z, v0.w));
            __nv_bfloat162 b2 = __float22bfloat162_rn(make_float2(v1.x, v1.y));
            __nv_bfloat162 b3 = __float22bfloat162_rn(make_float2(v1.z, v1.w));
            uint4 u;
            u.x = *(unsigned*)&b0; u.y = *(unsigned*)&b1; u.z = *(unsigned*)&b2; u.w = *(unsigned*)&b3;
            int phys = (ch & 8) | ((ch ^ r) & 7);
            *(uint4*)(dstr + (size_t)tile * 32768 + phys * 8) = u;
        }
#pragma unroll
        for (int o = 16; o; o >>= 1) s += __shfl_xor_sync(~0u, s, o);
        if (!lane) d_scratch[OFF_RS + (size_t)b * NN + row0 + r] = s;
    }

    // ---- gather x_t (transposed bf16) + zero h columns ----
    {
        const float2* rp = (const float2*)recent;
        for (int t = 0; t < TT; t++) {
            float2 v = rp[(size_t)(b * TT + t) * NN + n0];
            d_xt[((size_t)b * 48 + 2 * t) * NN + n0]     = __float2bfloat16_rn(v.x);
            d_xt[((size_t)b * 48 + 2 * t + 1) * NN + n0] = __float2bfloat16_rn(v.y);
        }
        __nv_bfloat16 z = __float2bfloat16_rn(0.f);
        for (int c = 0; c < 32; c++) d_xbf[((size_t)b * 48 + c) * NN + n0] = z;
    }

    float h1[16], h2[16], uu[16], ah2s[16], ah1p[16];
#pragma unroll
    for (int k = 0; k < 16; k++) { h1[k] = 0.f; h2[k] = 0.f; }

    gridbar();
    asm volatile("fence.proxy.async;" ::: "memory");   // generic pack writes -> TMA reads

    // ---- A @ x_t for all 24 timesteps (CTA-local outputs) ----
    for (int g = 0; g < 3; g++) {
        float a16[2][2][4];
        gemmP<16>(pk, d_xt + ((size_t)b * 48 + g * 16) * NN, smem_u, a16);
        stageStore<16>(stage, a16);
        __syncthreads();
        float* axp = d_scratch + OFF_AX + (size_t)g * (BB * NN * 16) + r0 * 16;
        const float* srow = stage + tid * 33;
#pragma unroll
        for (int q = 0; q < 4; q++)
            ((float4*)axp)[q] = make_float4(srow[4 * q], srow[4 * q + 1], srow[4 * q + 2], srow[4 * q + 3]);
        __syncthreads();
    }

    const __nv_bfloat16* xbB = d_xbf + (size_t)b * 48 * NN;
    __nv_bfloat16* xo_h1 = d_xbf + ((size_t)b * 48 + 0) * NN + n0;
    __nv_bfloat16* xo_h2 = d_xbf + ((size_t)b * 48 + 16) * NN + n0;
    __nv_bfloat16* xo_rh = d_xbf + ((size_t)b * 48 + 32) * NN + n0;

    const unsigned long long* W1ru = (const unsigned long long*)(smem_u + SW_W1RU);
    const unsigned long long* W2ru = (const unsigned long long*)(smem_u + SW_W2RU);
    const unsigned long long* W1cp = (const unsigned long long*)(smem_u + SW_W1CP);
    const unsigned long long* W2cp = (const unsigned long long*)(smem_u + SW_W2CP);
    const unsigned long long* B1ru = (const unsigned long long*)(smem_u + SW_B1RU);
    const unsigned long long* B2ru = (const unsigned long long*)(smem_u + SW_B2RU);
    const unsigned long long* B1cp = (const unsigned long long*)(smem_u + SW_B1CP);
    const unsigned long long* B2cp = (const unsigned long long*)(smem_u + SW_B2CP);

    for (int t = 0; t < TT; t++) {
        const int g = t >> 3, p = t & 7;
        const float* axp = d_scratch + OFF_AX + (size_t)g * (BB * NN * 16) + r0 * 16 + p * 2;

        // ---- phase 1: [A@h1 | A@h2], gates1 ----
        {
            float a32[2][4][4];
            gemmP<32>(pk, xbB, smem_u, a32);
            stageStore<32>(stage, a32);
            __syncthreads();
            const float* srow = stage + tid * 33;
            float2 axv = *(const float2*)axp;
            float xh[18];
            xh[0] = axv.x; xh[1] = axv.y;
#pragma unroll
            for (int k = 0; k < 16; k++) { xh[2 + k] = srow[k]; ah2s[k] = srow[16 + k]; }
#pragma unroll
            for (int j = 0; j < 16; j++) {
                unsigned long long s = B1ru[j];
#pragma unroll
                for (int k = 0; k < 18; k++) fma2(s, dup2(xh[k]), W1ru[j * 18 + k]);
                float sr, su; unpack2(s, sr, su);
                uu[j] = sigf(su);
                xo_rh[(size_t)j * NN] = __float2bfloat16_rn(sigf(sr) * h1[j]);
            }
            __syncthreads();
        }
        gridbar();

        // ---- phase 2: A@(r1*h1), gates2 -> h1' ----
        {
            float a16[2][2][4];
            gemmP<16>(pk, xbB + (size_t)32 * NN, smem_u, a16);
            stageStore<16>(stage, a16);
            __syncthreads();
            const float* srow = stage + tid * 33;
            float2 axv = *(const float2*)axp;
            float xh[18];
            xh[0] = axv.x; xh[1] = axv.y;
#pragma unroll
            for (int k = 0; k < 16; k++) xh[2 + k] = srow[k];
            unsigned long long sm[8];
#pragma unroll
            for (int m = 0; m < 8; m++) sm[m] = B1cp[m];
#pragma unroll
            for (int k = 0; k < 18; k++) {
                unsigned long long a = dup2(xh[k]);
#pragma unroll
                for (int m = 0; m < 8; m++) fma2(sm[m], a, W1cp[k * 8 + m]);
            }
#pragma unroll
            for (int m = 0; m < 8; m++) {
                float c0, c1; unpack2(sm[m], c0, c1);
                int j = 2 * m;
                h1[j]     = uu[j]     * h1[j]     + (1.f - uu[j])     * tanhf(c0);
                h1[j + 1] = uu[j + 1] * h1[j + 1] + (1.f - uu[j + 1]) * tanhf(c1);
                xo_h1[(size_t)j * NN]       = __float2bfloat16_rn(h1[j]);
                xo_h1[(size_t)(j + 1) * NN] = __float2bfloat16_rn(h1[j + 1]);
            }
            __syncthreads();
        }
        gridbar();

        // ---- phase 3: A@h1', gates3 ----
        {
            float a16[2][2][4];
            gemmP<16>(pk, xbB, smem_u, a16);
            stageStore<16>(stage, a16);
            __syncthreads();
            const float* srow = stage + tid * 33;
#pragma unroll
            for (int k = 0; k < 16; k++) ah1p[k] = srow[k];
#pragma unroll
            for (int j = 0; j < 16; j++) {
                unsigned long long s = B2ru[j];
#pragma unroll
                for (int k = 0; k < 16; k++) fma2(s, dup2(ah1p[k]), W2ru[j * 32 + k]);
#pragma unroll
                for (int k = 0; k < 16; k++) fma2(s, dup2(ah2s[k]), W2ru[j * 32 + 16 + k]);
                float sr, su; unpack2(s, sr, su);
                uu[j] = sigf(su);
                xo_rh[(size_t)j * NN] = __float2bfloat16_rn(sigf(sr) * h2[j]);
            }
            __syncthreads();
        }
        gridbar();

        // ---- phase 4: A@(r2*h2), gates4 -> h2' ----
        {
            float a16[2][2][4];
            gemmP<16>(pk, xbB + (size_t)32 * NN, smem_u, a16);
            stageStore<16>(stage, a16);
            __syncthreads();
            const float* srow = stage + tid * 33;
            unsigned long long sm[8];
#pragma unroll
            for (int m = 0; m < 8; m++) sm[m] = B2cp[m];
#pragma unroll
            for (int k = 0; k < 16; k++) {
                unsigned long long a = dup2(ah1p[k]);
#pragma unroll
                for (int m = 0; m < 8; m++) fma2(sm[m], a, W2cp[k * 8 + m]);
            }
#pragma unroll
            for (int k = 0; k < 16; k++) {
                unsigned long long a = dup2(srow[k]);
#pragma unroll
                for (int m = 0; m < 8; m++) fma2(sm[m], a, W2cp[(16 + k) * 8 + m]);
            }
#pragma unroll
            for (int m = 0; m < 8; m++) {
                float c0, c1; unpack2(sm[m], c0, c1);
                int j = 2 * m;
                h2[j]     = uu[j]     * h2[j]     + (1.f - uu[j])     * tanhf(c0);
                h2[j + 1] = uu[j + 1] * h2[j + 1] + (1.f - uu[j + 1]) * tanhf(c1);
                xo_h2[(size_t)j * NN]       = __float2bfloat16_rn(h2[j]);
                xo_h2[(size_t)(j + 1) * NN] = __float2bfloat16_rn(h2[j + 1]);
            }
            __syncthreads();
        }
        gridbar();
    }

    // ---- final: A@h2 + folded trend/feat, tanh, write output ----
    {
        float a16[2][2][4];
        gemmP<16>(pk, xbB + (size_t)16 * NN, smem_u, a16);
        stageStore<16>(stage, a16);
        __syncthreads();
        const float* srow = stage + tid * 33;
        const float* gw = (const float*)(smem_u + SW_GCNW);
        const float* gb = (const float*)(smem_u + SW_GCNB);
        float rs = d_scratch[OFF_RS + r0];
        float o0 = gb[0] + rs * d_scratch[OFF_TVF + b * 2];
        float o1 = gb[1] + rs * d_scratch[OFF_TVF + b * 2 + 1];
#pragma unroll
        for (int c = 0; c < 16; c++) {
            o0 += srow[c] * gw[c];
            o1 += srow[c] * gw[16 + c];
        }
        *(float2*)(out + r0 * 2) = make_float2(tanhf(o0), tanhf(o1));
    }
}

// ---- 2-layer LSTM + feat FF folded into tvf (B,2) ----
__global__ __launch_bounds__(1024) void prepK(
    const float* __restrict__ trend, const float* __restrict__ tf,
    const float* __restrict__ Wih0, const float* __restrict__ Whh0,
    const float* __restrict__ bih0, const float* __restrict__ bhh0,
    const float* __restrict__ Wih1, const float* __restrict__ Whh1,
    const float* __restrict__ bih1, const float* __restrict__ bhh1,
    const float* __restrict__ ffW, const float* __restrict__ ffb,
    const float* __restrict__ gcnW) {
    __shared__ float h1s[32][32], c1s[32][32], h2s[32][32], c2s[32][32], feats[32][32];
    int tid = threadIdx.x;
    int b = tid >> 5, j = tid & 31;
    h1s[b][j] = 0.f; c1s[b][j] = 0.f; h2s[b][j] = 0.f; c2s[b][j] = 0.f;
    __syncthreads();

    for (int t = 0; t < TT; t++) {
        float x0 = trend[(b * TT + t) * 2 + 0];
        float x1 = trend[(b * TT + t) * 2 + 1];
        float g0[4];
#pragma unroll
        for (int g = 0; g < 4; g++) {
            int idx = g * 32 + j;
            float s = bih0[idx] + bhh0[idx] + Wih0[idx * 2] * x0 + Wih0[idx * 2 + 1] * x1;
            for (int k = 0; k < 32; k++) s += Whh0[idx * 32 + k] * h1s[b][k];
            g0[g] = s;
        }
        float c1 = sigf(g0[1]) * c1s[b][j] + sigf(g0[0]) * tanhf(g0[2]);
        float h1 = sigf(g0[3]) * tanhf(c1);
        __syncthreads();
        h1s[b][j] = h1; c1s[b][j] = c1;
        __syncthreads();

        float g1[4];
#pragma unroll
        for (int g = 0; g < 4; g++) {
            int idx = g * 32 + j;
            float s = bih1[idx] + bhh1[idx];
            for (int k = 0; k < 32; k++)
                s += Wih1[idx * 32 + k] * h1s[b][k] + Whh1[idx * 32 + k] * h2s[b][k];
            g1[g] = s;
        }
        float c2 = sigf(g1[1]) * c2s[b][j] + sigf(g1[0]) * tanhf(g1[2]);
        float h2 = sigf(g1[3]) * tanhf(c2);
        __syncthreads();
        h2s[b][j] = h2; c2s[b][j] = c2;
        __syncthreads();
    }

    float s = ffb[j];
    for (int k = 0; k < 31; k++) s += tf[b * 31 + k] * ffW[j * 31 + k];
    feats[b][j] = fmaxf(s, 0.f);
    __syncthreads();

    if (tid < 64) {
        int bb = tid >> 1, f = tid & 1;
        float s2 = 0.f;
        for (int c = 0; c < 32; c++)
            s2 += h2s[bb][c] * gcnW[f * 80 + 16 + c] + feats[bb][c] * gcnW[f * 80 + 48 + c];
        d_scratch[OFF_TVF + bb * 2 + f] = s2;
    }
}

// ================================== launcher ===================================
extern "C" void kernel_launch(void* const* d_in, const int* in_sizes, int n_in,
                              void* d_out, int out_size) {
    const float* recent = (const float*)d_in[0];
    const float* trend  = (const float*)d_in[1];
    const float* A      = (const float*)d_in[2];
    const float* tf     = (const float*)d_in[3];
    const float* g1rW = (const float*)d_in[4],  *g1rb = (const float*)d_in[5];
    const float* g1uW = (const float*)d_in[6],  *g1ub = (const float*)d_in[7];
    const float* g1cW = (const float*)d_in[8],  *g1cb = (const float*)d_in[9];
    const float* g2rW = (const float*)d_in[10], *g2rb = (const float*)d_in[11];
    const float* g2uW = (const float*)d_in[12], *g2ub = (const float*)d_in[13];
    const float* g2cW = (const float*)d_in[14], *g2cb = (const float*)d_in[15];
    const float* Wih0 = (const float*)d_in[16], *Whh0 = (const float*)d_in[17];
    const float* bih0 = (const float*)d_in[18], *bhh0 = (const float*)d_in[19];
    const float* Wih1 = (const float*)d_in[20], *Whh1 = (const float*)d_in[21];
    const float* bih1 = (const float*)d_in[22], *bhh1 = (const float*)d_in[23];
    const float* ffW  = (const float*)d_in[24], *ffb  = (const float*)d_in[25];
    const float* gcnW = (const float*)d_in[26], *gcnb = (const float*)d_in[27];
    float* out = (float*)d_out;

    cudaFuncSetAttribute(persistK, cudaFuncAttributeMaxDynamicSharedMemorySize, SMEM_BYTES);

    prepK<<<1, 1024>>>(trend, tf, Wih0, Whh0, bih0, bhh0,
                       Wih1, Whh1, bih1, bhh1, ffW, ffb, gcnW);
    persistK<<<NCTA, NTHR, SMEM_BYTES>>>(A, recent,
                                         g1rW, g1rb, g1uW, g1ub, g1cW, g1cb,
                                         g2rW, g2rb, g2uW, g2ub, g2cW, g2cb,
                                         gcnW, gcnb, out);
}

// round 7
// speedup vs baseline: 2.5599x; 1.0087x over previous
#include <cuda_runtime.h>
#include <cuda_bf16.h>
#include <math.h>

#define BB 32
#define TT 24
#define NN 1024
#define KC 128
#define KT2 (NN / KC)          // 8 tiles
#define NCTA 128
#define NTHR 256
#define GRP 4                  // CTAs per batch

// ---------------- fp32 scratch ----------------
#define OFF_AX   0                          // 3 groups x (B,N,16) = A@x_t
#define OFF_RS   (3 * BB * NN * 16)         // (B,N) rowsum(A)
#define OFF_TVF  (OFF_RS + BB * NN)         // (B,2)
#define SCRATCH_FLOATS (OFF_TVF + BB * 2)

__device__ float d_scratch[SCRATCH_FLOATS];
// A bf16, tile-major packed + swizzled: per CTA slice 8 tiles x 64KB contiguous
__device__ __nv_bfloat16 d_Apk[(size_t)BB * NN * NN];
__device__ __nv_bfloat16 d_xbf[(size_t)BB * 48 * NN];     // X^T: 0-15 h1, 16-31 h2, 32-47 r*h
__device__ __nv_bfloat16 d_xt [(size_t)BB * 48 * NN];     // gathered x_t, transposed
// per-batch barrier state, one padded line per batch
__device__ unsigned g_bcnt[BB * 32];
__device__ volatile unsigned g_bgen[BB * 32];

// smem word-offsets (dynamic)
#define SW_AS   0        // A tiles: 2 x 16384 words (64KB each)
#define SW_XS   32768    // X tiles: 2 x 32 x 68 words
#define SW_MB   37120    // 2 mbarriers
#define SW_W1RU 37128
#define SW_W2RU 37704
#define SW_W1CP 38728
#define SW_W2CP 39016
#define SW_B1RU 39528
#define SW_B2RU 39560
#define SW_B1CP 39592
#define SW_B2CP 39608
#define SW_GCNW 39624
#define SW_GCNB 39656
#define SW_STG  39658    // stage: 256 x 33 floats (dedicated, no alias with A bufs)
#define SMEM_WORDS (SW_STG + 256 * 33)
#define SMEM_BYTES (SMEM_WORDS * 4 + 8)

__device__ __forceinline__ float sigf(float x) { return 1.0f / (1.0f + expf(-x)); }

__device__ __forceinline__ void cpa16s(unsigned* sm, const void* gm) {
    unsigned sa = (unsigned)__cvta_generic_to_shared(sm);
    asm volatile("cp.async.cg.shared.global [%0], [%1], 16;" :: "r"(sa), "l"(gm) : "memory");
}
#define CP_COMMIT() asm volatile("cp.async.commit_group;" ::: "memory")
#define CP_WAIT(n)  asm volatile("cp.async.wait_group %0;" :: "n"(n) : "memory")

__device__ __forceinline__ unsigned long long dup2(float x) {
    unsigned long long r; unsigned u = __float_as_uint(x);
    asm("mov.b64 %0, {%1, %1};" : "=l"(r) : "r"(u));
    return r;
}
__device__ __forceinline__ void fma2(unsigned long long& s, unsigned long long a, unsigned long long w) {
    asm("fma.rn.f32x2 %0, %1, %2, %0;" : "+l"(s) : "l"(a), "l"(w));
}
__device__ __forceinline__ void unpack2(unsigned long long s, float& x, float& y) {
    unsigned lo, hi; asm("mov.b64 {%0, %1}, %2;" : "=r"(lo), "=r"(hi) : "l"(s));
    x = __uint_as_float(lo); y = __uint_as_float(hi);
}

__device__ __forceinline__ void mbwait(unsigned mb, int phase) {
    asm volatile(
        "{\n\t.reg .pred P;\n\t"
        "W_%=:\n\t"
        "mbarrier.try_wait.parity.acquire.cta.shared::cta.b64 P, [%0], %1, 0x989680;\n\t"
        "@P bra.uni D_%=;\n\t"
        "bra.uni W_%=;\n\t"
        "D_%=:\n\t}"
        :: "r"(mb), "r"((unsigned)phase) : "memory");
}

// per-batch barrier: EXACT R4 gridbar fence structure (all-thread gpu fence
// before the quorum), membership reduced to the GRP CTAs of one batch.
__device__ __forceinline__ void batchbar(int b) {
    __threadfence();
    __syncthreads();
    if (threadIdx.x == 0) {
        unsigned gen = g_bgen[b * 32];
        if (atomicAdd(&g_bcnt[b * 32], 1) == GRP - 1) {
            g_bcnt[b * 32] = 0;
            __threadfence();
            g_bgen[b * 32] = gen + 1;
        } else {
            while (g_bgen[b * 32] == gen) __nanosleep(32);
        }
        __threadfence();
    }
    __syncthreads();
}

// ---------- GEMM phase: acc[256 own rows x C] = A_own(256x1024) @ X^T(C x 1024)^T ----------
// A tiles arrive via cp.async.bulk (64KB, mbarrier), X tiles via cp.async.
template <int C>
__device__ __forceinline__ void gemmP(const __nv_bfloat16* __restrict__ Apk,
                                      const __nv_bfloat16* __restrict__ Xb,
                                      unsigned* smem_u, float acc[2][C / 8][4]) {
    const int tid = threadIdx.x, w = tid >> 5, lane = tid & 31;
    const unsigned aB  = (unsigned)__cvta_generic_to_shared(smem_u + SW_AS);
    const unsigned mb0 = (unsigned)__cvta_generic_to_shared(smem_u + SW_MB);

#pragma unroll
    for (int mt = 0; mt < 2; mt++)
#pragma unroll
        for (int nt = 0; nt < C / 8; nt++)
#pragma unroll
            for (int q = 0; q < 4; q++) acc[mt][nt][q] = 0.f;

    auto issueA = [&](int buf, int kt) {
        if (tid == 0) {
            unsigned mb = mb0 + buf * 8;
            asm volatile("mbarrier.arrive.expect_tx.shared.b64 _, [%0], %1;"
                         :: "r"(mb), "r"(65536u) : "memory");
            asm volatile("cp.async.bulk.shared::cluster.global.mbarrier::complete_tx::bytes "
                         "[%0], [%1], %2, [%3];"
                         :: "r"(aB + buf * 65536), "l"(Apk + (size_t)kt * 32768),
                            "r"(65536u), "r"(mb)
                         : "memory");
        }
    };
    auto issueX = [&](int buf, int kt) {
        unsigned* Xd = smem_u + SW_XS + buf * 2176;
#pragma unroll
        for (int q = 0; q < C / 16; q++) {
            int i = tid + q * 256;
            int c = i >> 4, ch = i & 15;
            cpa16s(Xd + c * 68 + ch * 4, Xb + (size_t)c * NN + kt * 128 + ch * 8);
        }
        CP_COMMIT();
    };

    issueA(0, 0); issueA(1, 1);
    issueX(0, 0); issueX(1, 1);

    int ph0 = 0, ph1 = 0;
    const unsigned boff = ((unsigned)(lane & 7) * 68 + ((lane >> 3) & 1) * 4) * 4;

    for (int kt = 0; kt < KT2; kt++) {
        const int cur = kt & 1;
        if (kt < KT2 - 1) { CP_WAIT(1); } else { CP_WAIT(0); }
        if (cur == 0) { mbwait(mb0, ph0); ph0 ^= 1; }
        else          { mbwait(mb0 + 8, ph1); ph1 ^= 1; }

        const unsigned aBase = aB + cur * 65536;
        const unsigned xB = (unsigned)__cvta_generic_to_shared(smem_u + SW_XS + cur * 2176);
#pragma unroll
        for (int ks = 0; ks < 8; ks++) {
            unsigned bf[C / 8][2];
#pragma unroll
            for (int nt = 0; nt < C / 8; nt++) {
                unsigned ad = xB + boff + (unsigned)nt * 8 * 68 * 4 + (unsigned)ks * 32;
                asm volatile("ldmatrix.sync.aligned.m8n8.x2.shared.b16 {%0,%1}, [%2];"
                             : "=r"(bf[nt][0]), "=r"(bf[nt][1]) : "r"(ad));
            }
#pragma unroll
            for (int mt = 0; mt < 2; mt++) {
                const int r = w * 32 + mt * 16 + (lane & 15);
                const int ci = ks * 2 + (lane >> 4);
                const int phys = (ci & 8) | ((ci ^ r) & 7);
                unsigned a0, a1, a2, a3;
                unsigned ad = aBase + (unsigned)r * 256 + (unsigned)phys * 16;
                asm volatile("ldmatrix.sync.aligned.m8n8.x4.shared.b16 {%0,%1,%2,%3}, [%4];"
                             : "=r"(a0), "=r"(a1), "=r"(a2), "=r"(a3) : "r"(ad));
#pragma unroll
                for (int nt = 0; nt < C / 8; nt++) {
                    asm volatile(
                        "mma.sync.aligned.m16n8k16.row.col.f32.bf16.bf16.f32 "
                        "{%0,%1,%2,%3},{%4,%5,%6,%7},{%8,%9},{%0,%1,%2,%3};"
                        : "+f"(acc[mt][nt][0]), "+f"(acc[mt][nt][1]),
                          "+f"(acc[mt][nt][2]), "+f"(acc[mt][nt][3])
                        : "r"(a0), "r"(a1), "r"(a2), "r"(a3),
                          "r"(bf[nt][0]), "r"(bf[nt][1]));
                }
            }
        }
        __syncthreads();
        if (kt + 2 < KT2) { issueA(cur, kt + 2); issueX(cur, kt + 2); }
    }
}

// write acc fragments to smem stage (256 rows, pitch 33)
template <int C>
__device__ __forceinline__ void stageStore(float* stage, const float acc[2][C / 8][4]) {
    const int lane = threadIdx.x & 31, w = threadIdx.x >> 5;
    const int g = lane >> 2, c2 = (lane & 3) * 2;
#pragma unroll
    for (int mt = 0; mt < 2; mt++) {
        int rr = w * 32 + mt * 16 + g;
#pragma unroll
        for (int nt = 0; nt < C / 8; nt++) {
            int col = nt * 8 + c2;
            stage[rr * 33 + col]           = acc[mt][nt][0];
            stage[rr * 33 + col + 1]       = acc[mt][nt][1];
            stage[(rr + 8) * 33 + col]     = acc[mt][nt][2];
            stage[(rr + 8) * 33 + col + 1] = acc[mt][nt][3];
        }
    }
}

// ================= persistent kernel =================
__global__ void __launch_bounds__(NTHR, 1) persistK(
    const float* __restrict__ A, const float* __restrict__ recent,
    const float* __restrict__ g1rW, const float* __restrict__ g1rb,
    const float* __restrict__ g1uW, const float* __restrict__ g1ub,
    const float* __restrict__ g1cW, const float* __restrict__ g1cb,
    const float* __restrict__ g2rW, const float* __restrict__ g2rb,
    const float* __restrict__ g2uW, const float* __restrict__ g2ub,
    const float* __restrict__ g2cW, const float* __restrict__ g2cb,
    const float* __restrict__ gcnW, const float* __restrict__ gcnb,
    float* __restrict__ out) {
    extern __shared__ unsigned smem_u[];
    float* stage = (float*)(smem_u + SW_STG);

    const int tid = threadIdx.x, w = tid >> 5, lane = tid & 31;
    const int b = blockIdx.x >> 2, rb = blockIdx.x & 3;
    const int row0 = rb * 256, n0 = row0 + tid;
    const size_t r0 = (size_t)b * NN + n0;

    if (tid == 0) {
        unsigned mb = (unsigned)__cvta_generic_to_shared(smem_u + SW_MB);
        asm volatile("mbarrier.init.shared.b64 [%0], %1;" :: "r"(mb), "r"(1u) : "memory");
        asm volatile("mbarrier.init.shared.b64 [%0], %1;" :: "r"(mb + 8), "r"(1u) : "memory");
    }

    // ---- weight tables into smem ----
    {
        float2* W1 = (float2*)(smem_u + SW_W1RU);
        for (int i = tid; i < 288; i += NTHR) W1[i] = make_float2(g1rW[i], g1uW[i]);
        float2* W2 = (float2*)(smem_u + SW_W2RU);
        for (int i = tid; i < 512; i += NTHR) W2[i] = make_float2(g2rW[i], g2uW[i]);
        float2* C1 = (float2*)(smem_u + SW_W1CP);
        for (int i = tid; i < 144; i += NTHR) {
            int k = i >> 3, m = i & 7;
            C1[i] = make_float2(g1cW[(2 * m) * 18 + k], g1cW[(2 * m + 1) * 18 + k]);
        }
        float2* C2 = (float2*)(smem_u + SW_W2CP);
        for (int i = tid; i < 256; i += NTHR) {
            int k = i >> 3, m = i & 7;
            C2[i] = make_float2(g2cW[(2 * m) * 32 + k], g2cW[(2 * m + 1) * 32 + k]);
        }
        if (tid < 16) ((float2*)(smem_u + SW_B1RU))[tid] = make_float2(g1rb[tid], g1ub[tid]);
        else if (tid < 32) ((float2*)(smem_u + SW_B2RU))[tid - 16] = make_float2(g2rb[tid - 16], g2ub[tid - 16]);
        else if (tid < 40) ((float2*)(smem_u + SW_B1CP))[tid - 32] = make_float2(g1cb[2 * (tid - 32)], g1cb[2 * (tid - 32) + 1]);
        else if (tid < 48) ((float2*)(smem_u + SW_B2CP))[tid - 40] = make_float2(g2cb[2 * (tid - 40)], g2cb[2 * (tid - 40) + 1]);
        else if (tid < 80) { int i = tid - 48; ((float*)(smem_u + SW_GCNW))[i] = gcnW[(i >> 4) * 80 + (i & 15)]; }
        else if (tid < 82) ((float*)(smem_u + SW_GCNB))[tid - 80] = gcnb[tid - 80];
    }

    // ---- pack own A slice: fp32 -> bf16, tile-major, swizzled; fused exact rowsum ----
    const float* Arow = A + ((size_t)b * NN + row0) * NN;
    __nv_bfloat16* pk = d_Apk + (size_t)blockIdx.x * (256 * NN);
    for (int j = 0; j < 32; j++) {
        const int r = w * 32 + j;
        const float* srcr = Arow + (size_t)r * NN;
        __nv_bfloat16* dstr = pk + r * 128;
        float s = 0.f;
#pragma unroll
        for (int q = 0; q < 4; q++) {
            int ci = lane + q * 32;
            int tile = ci >> 4, ch = ci & 15;
            const float* sp = srcr + ci * 8;
            float4 v0 = *(const float4*)sp;
            float4 v1 = *(const float4*)(sp + 4);
            s += (v0.x + v0.y) + (v0.z + v0.w) + (v1.x + v1.y) + (v1.z + v1.w);
            __nv_bfloat162 b0 = __float22bfloat162_rn(make_float2(v0.x, v0.y));
            __nv_bfloat162 b1 = __float22bfloat162_rn(make_float2(v0.z, v0.w));
            __nv_bfloat162 b2 = __float22bfloat162_rn(make_float2(v1.x, v1.y));
            __nv_bfloat162 b3 = __float22bfloat162_rn(make_float2(v1.z, v1.w));
            uint4 u;
            u.x = *(unsigned*)&b0; u.y = *(unsigned*)&b1; u.z = *(unsigned*)&b2; u.w = *(unsigned*)&b3;
            int phys = (ch & 8) | ((ch ^ r) & 7);
            *(uint4*)(dstr + (size_t)tile * 32768 + phys * 8) = u;
        }
#pragma unroll
        for (int o = 16; o; o >>= 1) s += __shfl_xor_sync(~0u, s, o);
        if (!lane) d_scratch[OFF_RS + (size_t)b * NN + row0 + r] = s;
    }

    // ---- gather x_t (transposed bf16) + zero h columns ----
    {
        const float2* rp = (const float2*)recent;
        for (int t = 0; t < TT; t++) {
            float2 v = rp[(size_t)(b * TT + t) * NN + n0];
            d_xt[((size_t)b * 48 + 2 * t) * NN + n0]     = __float2bfloat16_rn(v.x);
            d_xt[((size_t)b * 48 + 2 * t + 1) * NN + n0] = __float2bfloat16_rn(v.y);
        }
        __nv_bfloat16 z = __float2bfloat16_rn(0.f);
        for (int c = 0; c < 32; c++) d_xbf[((size_t)b * 48 + c) * NN + n0] = z;
    }

    float h1[16], h2[16], uu[16], ah2s[16], ah1p[16];
#pragma unroll
    for (int k = 0; k < 16; k++) { h1[k] = 0.f; h2[k] = 0.f; }

    batchbar(b);
    asm volatile("fence.proxy.async;" ::: "memory");   // pack writes + mbar init -> async proxy

    // ---- A @ x_t for all 24 timesteps (CTA-local outputs) ----
    for (int g = 0; g < 3; g++) {
        float a16[2][2][4];
        gemmP<16>(pk, d_xt + ((size_t)b * 48 + g * 16) * NN, smem_u, a16);
        stageStore<16>(stage, a16);
        __syncthreads();
        float* axp = d_scratch + OFF_AX + (size_t)g * (BB * NN * 16) + r0 * 16;
        const float* srow = stage + tid * 33;
#pragma unroll
        for (int q = 0; q < 4; q++)
            ((float4*)axp)[q] = make_float4(srow[4 * q], srow[4 * q + 1], srow[4 * q + 2], srow[4 * q + 3]);
        __syncthreads();
    }

    const __nv_bfloat16* xbB = d_xbf + (size_t)b * 48 * NN;
    __nv_bfloat16* xo_h1 = d_xbf + ((size_t)b * 48 + 0) * NN + n0;
    __nv_bfloat16* xo_h2 = d_xbf + ((size_t)b * 48 + 16) * NN + n0;
    __nv_bfloat16* xo_rh = d_xbf + ((size_t)b * 48 + 32) * NN + n0;

    const unsigned long long* W1ru = (const unsigned long long*)(smem_u + SW_W1RU);
    const unsigned long long* W2ru = (const unsigned long long*)(smem_u + SW_W2RU);
    const unsigned long long* W1cp = (const unsigned long long*)(smem_u + SW_W1CP);
    const unsigned long long* W2cp = (const unsigned long long*)(smem_u + SW_W2CP);
    const unsigned long long* B1ru = (const unsigned long long*)(smem_u + SW_B1RU);
    const unsigned long long* B2ru = (const unsigned long long*)(smem_u + SW_B2RU);
    const unsigned long long* B1cp = (const unsigned long long*)(smem_u + SW_B1CP);
    const unsigned long long* B2cp = (const unsigned long long*)(smem_u + SW_B2CP);

    for (int t = 0; t < TT; t++) {
        const int g = t >> 3, p = t & 7;
        const float* axp = d_scratch + OFF_AX + (size_t)g * (BB * NN * 16) + r0 * 16 + p * 2;

        // ---- phase 1: [A@h1 | A@h2], gates1 ----
        {
            float a32[2][4][4];
            gemmP<32>(pk, xbB, smem_u, a32);
            stageStore<32>(stage, a32);
            __syncthreads();
            const float* srow = stage + tid * 33;
            float2 axv = *(const float2*)axp;
            float xh[18];
            xh[0] = axv.x; xh[1] = axv.y;
#pragma unroll
            for (int k = 0; k < 16; k++) { xh[2 + k] = srow[k]; ah2s[k] = srow[16 + k]; }
#pragma unroll
            for (int j = 0; j < 16; j++) {
                unsigned long long s = B1ru[j];
#pragma unroll
                for (int k = 0; k < 18; k++) fma2(s, dup2(xh[k]), W1ru[j * 18 + k]);
                float sr, su; unpack2(s, sr, su);
                uu[j] = sigf(su);
                xo_rh[(size_t)j * NN] = __float2bfloat16_rn(sigf(sr) * h1[j]);
            }
            __syncthreads();
        }
        batchbar(b);

        // ---- phase 2: A@(r1*h1), gates2 -> h1' ----
        {
            float a16[2][2][4];
            gemmP<16>(pk, xbB + (size_t)32 * NN, smem_u, a16);
            stageStore<16>(stage, a16);
            __syncthreads();
            const float* srow = stage + tid * 33;
            float2 axv = *(const float2*)axp;
            float xh[18];
            xh[0] = axv.x; xh[1] = axv.y;
#pragma unroll
            for (int k = 0; k < 16; k++) xh[2 + k] = srow[k];
            unsigned long long sm[8];
#pragma unroll
            for (int m = 0; m < 8; m++) sm[m] = B1cp[m];
#pragma unroll
            for (int k = 0; k < 18; k++) {
                unsigned long long a = dup2(xh[k]);
#pragma unroll
                for (int m = 0; m < 8; m++) fma2(sm[m], a, W1cp[k * 8 + m]);
            }
#pragma unroll
            for (int m = 0; m < 8; m++) {
                float c0, c1; unpack2(sm[m], c0, c1);
                int j = 2 * m;
                h1[j]     = uu[j]     * h1[j]     + (1.f - uu[j])     * tanhf(c0);
                h1[j + 1] = uu[j + 1] * h1[j + 1] + (1.f - uu[j + 1]) * tanhf(c1);
                xo_h1[(size_t)j * NN]       = __float2bfloat16_rn(h1[j]);
                xo_h1[(size_t)(j + 1) * NN] = __float2bfloat16_rn(h1[j + 1]);
            }
            __syncthreads();
        }
        batchbar(b);

        // ---- phase 3: A@h1', gates3 ----
        {
            float a16[2][2][4];
            gemmP<16>(pk, xbB, smem_u, a16);
            stageStore<16>(stage, a16);
            __syncthreads();
            const float* srow = stage + tid * 33;
#pragma unroll
            for (int k = 0; k < 16; k++) ah1p[k] = srow[k];
#pragma unroll
            for (int j = 0; j < 16; j++) {
                unsigned long long s = B2ru[j];
#pragma unroll
                for (int k = 0; k < 16; k++) fma2(s, dup2(ah1p[k]), W2ru[j * 32 + k]);
#pragma unroll
                for (int k = 0; k < 16; k++) fma2(s, dup2(ah2s[k]), W2ru[j * 32 + 16 + k]);
                float sr, su; unpack2(s, sr, su);
                uu[j] = sigf(su);
                xo_rh[(size_t)j * NN] = __float2bfloat16_rn(sigf(sr) * h2[j]);
            }
            __syncthreads();
        }
        batchbar(b);

        // ---- phase 4: A@(r2*h2), gates4 -> h2' ----
        {
            float a16[2][2][4];
            gemmP<16>(pk, xbB + (size_t)32 * NN, smem_u, a16);
            stageStore<16>(stage, a16);
            __syncthreads();
            const float* srow = stage + tid * 33;
            unsigned long long sm[8];
#pragma unroll
            for (int m = 0; m < 8; m++) sm[m] = B2cp[m];
#pragma unroll
            for (int k = 0; k < 16; k++) {
                unsigned long long a = dup2(ah1p[k]);
#pragma unroll
                for (int m = 0; m < 8; m++) fma2(sm[m], a, W2cp[k * 8 + m]);
            }
#pragma unroll
            for (int k = 0; k < 16; k++) {
                unsigned long long a = dup2(srow[k]);
#pragma unroll
                for (int m = 0; m < 8; m++) fma2(sm[m], a, W2cp[(16 + k) * 8 + m]);
            }
#pragma unroll
            for (int m = 0; m < 8; m++) {
                float c0, c1; unpack2(sm[m], c0, c1);
                int j = 2 * m;
                h2[j]     = uu[j]     * h2[j]     + (1.f - uu[j])     * tanhf(c0);
                h2[j + 1] = uu[j + 1] * h2[j + 1] + (1.f - uu[j + 1]) * tanhf(c1);
                xo_h2[(size_t)j * NN]       = __float2bfloat16_rn(h2[j]);
                xo_h2[(size_t)(j + 1) * NN] = __float2bfloat16_rn(h2[j + 1]);
            }
            __syncthreads();
        }
        batchbar(b);
    }

    // ---- final: A@h2 + folded trend/feat, tanh, write output ----
    {
        float a16[2][2][4];
        gemmP<16>(pk, xbB + (size_t)16 * NN, smem_u, a16);
        stageStore<16>(stage, a16);
        __syncthreads();
        const float* srow = stage + tid * 33;
        const float* gw = (const float*)(smem_u + SW_GCNW);
        const float* gb = (const float*)(smem_u + SW_GCNB);
        float rs = d_scratch[OFF_RS + r0];
        float o0 = gb[0] + rs * d_scratch[OFF_TVF + b * 2];
        float o1 = gb[1] + rs * d_scratch[OFF_TVF + b * 2 + 1];
#pragma unroll
        for (int c = 0; c < 16; c++) {
            o0 += srow[c] * gw[c];
            o1 += srow[c] * gw[16 + c];
        }
        *(float2*)(out + r0 * 2) = make_float2(tanhf(o0), tanhf(o1));
    }
}

// ---- 2-layer LSTM + feat FF folded into tvf (B,2) ----
__global__ __launch_bounds__(1024) void prepK(
    const float* __restrict__ trend, const float* __restrict__ tf,
    const float* __restrict__ Wih0, const float* __restrict__ Whh0,
    const float* __restrict__ bih0, const float* __restrict__ bhh0,
    const float* __restrict__ Wih1, const float* __restrict__ Whh1,
    const float* __restrict__ bih1, const float* __restrict__ bhh1,
    const float* __restrict__ ffW, const float* __restrict__ ffb,
    const float* __restrict__ gcnW) {
    __shared__ float h1s[32][32], c1s[32][32], h2s[32][32], c2s[32][32], feats[32][32];
    int tid = threadIdx.x;
    int b = tid >> 5, j = tid & 31;
    h1s[b][j] = 0.f; c1s[b][j] = 0.f; h2s[b][j] = 0.f; c2s[b][j] = 0.f;
    __syncthreads();

    for (int t = 0; t < TT; t++) {
        float x0 = trend[(b * TT + t) * 2 + 0];
        float x1 = trend[(b * TT + t) * 2 + 1];
        float g0[4];
#pragma unroll
        for (int g = 0; g < 4; g++) {
            int idx = g * 32 + j;
            float s = bih0[idx] + bhh0[idx] + Wih0[idx * 2] * x0 + Wih0[idx * 2 + 1] * x1;
            for (int k = 0; k < 32; k++) s += Whh0[idx * 32 + k] * h1s[b][k];
            g0[g] = s;
        }
        float c1 = sigf(g0[1]) * c1s[b][j] + sigf(g0[0]) * tanhf(g0[2]);
        float h1 = sigf(g0[3]) * tanhf(c1);
        __syncthreads();
        h1s[b][j] = h1; c1s[b][j] = c1;
        __syncthreads();

        float g1[4];
#pragma unroll
        for (int g = 0; g < 4; g++) {
            int idx = g * 32 + j;
            float s = bih1[idx] + bhh1[idx];
            for (int k = 0; k < 32; k++)
                s += Wih1[idx * 32 + k] * h1s[b][k] + Whh1[idx * 32 + k] * h2s[b][k];
            g1[g] = s;
        }
        float c2 = sigf(g1[1]) * c2s[b][j] + sigf(g1[0]) * tanhf(g1[2]);
        float h2 = sigf(g1[3]) * tanhf(c2);
        __syncthreads();
        h2s[b][j] = h2; c2s[b][j] = c2;
        __syncthreads();
    }

    float s = ffb[j];
    for (int k = 0; k < 31; k++) s += tf[b * 31 + k] * ffW[j * 31 + k];
    feats[b][j] = fmaxf(s, 0.f);
    __syncthreads();

    if (tid < 64) {
        int bb = tid >> 1, f = tid & 1;
        float s2 = 0.f;
        for (int c = 0; c < 32; c++)
            s2 += h2s[bb][c] * gcnW[f * 80 + 16 + c] + feats[bb][c] * gcnW[f * 80 + 48 + c];
        d_scratch[OFF_TVF + bb * 2 + f] = s2;
    }
}

// ================================== launcher ===================================
extern "C" void kernel_launch(void* const* d_in, const int* in_sizes, int n_in,
                              void* d_out, int out_size) {
    const float* recent = (const float*)d_in[0];
    const float* trend  = (const float*)d_in[1];
    const float* A      = (const float*)d_in[2];
    const float* tf     = (const float*)d_in[3];
    const float* g1rW = (const float*)d_in[4],  *g1rb = (const float*)d_in[5];
    const float* g1uW = (const float*)d_in[6],  *g1ub = (const float*)d_in[7];
    const float* g1cW = (const float*)d_in[8],  *g1cb = (const float*)d_in[9];
    const float* g2rW = (const float*)d_in[10], *g2rb = (const float*)d_in[11];
    const float* g2uW = (const float*)d_in[12], *g2ub = (const float*)d_in[13];
    const float* g2cW = (const float*)d_in[14], *g2cb = (const float*)d_in[15];
    const float* Wih0 = (const float*)d_in[16], *Whh0 = (const float*)d_in[17];
    const float* bih0 = (const float*)d_in[18], *bhh0 = (const float*)d_in[19];
    const float* Wih1 = (const float*)d_in[20], *Whh1 = (const float*)d_in[21];
    const float* bih1 = (const float*)d_in[22], *bhh1 = (const float*)d_in[23];
    const float* ffW  = (const float*)d_in[24], *ffb  = (const float*)d_in[25];
    const float* gcnW = (const float*)d_in[26], *gcnb = (const float*)d_in[27];
    float* out = (float*)d_out;

    cudaFuncSetAttribute(persistK, cudaFuncAttributeMaxDynamicSharedMemorySize, SMEM_BYTES);

    prepK<<<1, 1024>>>(trend, tf, Wih0, Whh0, bih0, bhh0,
                       Wih1, Whh1, bih1, bhh1, ffW, ffb, gcnW);
    persistK<<<NCTA, NTHR, SMEM_BYTES>>>(A, recent,
                                         g1rW, g1rb, g1uW, g1ub, g1cW, g1cb,
                                         g2rW, g2rb, g2uW, g2ub, g2cW, g2cb,
                                         gcnW, gcnb, out);
}

// round 8
// speedup vs baseline: 2.5769x; 1.0066x over previous
#include <cuda_runtime.h>
#include <cuda_bf16.h>
#include <math.h>

#define BB 32
#define TT 24
#define NN 1024
#define NCTA 128
#define NTHR 256
#define GRP 4                  // CTAs per batch

// ---------------- fp32 scratch ----------------
#define OFF_AX   0                          // 3 groups x (B,N,16) = A@x_t
#define OFF_RS   (3 * BB * NN * 16)         // (B,N) rowsum(A)
#define OFF_TVF  (OFF_RS + BB * NN)         // (B,2)
#define SCRATCH_FLOATS (OFF_TVF + BB * 2)

__device__ float d_scratch[SCRATCH_FLOATS];
// A bf16 packed in mma-fragment order: per CTA 32768 uint4
// index: ((blk*64 + ks)*32 + lane), blk = warp*2 + mt
__device__ uint4 d_Apk[(size_t)BB * NN * NN / 8];
__device__ __nv_bfloat16 d_xbf[(size_t)BB * 48 * NN];     // X^T: 0-15 h1, 16-31 h2, 32-47 r*h
__device__ __nv_bfloat16 d_xt [(size_t)BB * 48 * NN];     // gathered x_t, transposed
// per-batch barrier state, one padded line per batch
__device__ unsigned g_bcnt[BB * 32];
__device__ volatile unsigned g_bgen[BB * 32];

// smem word-offsets (dynamic)
#define XPW 516          // X smem pitch in words (2048B data + 16B pad)
#define SW_X    0        // X: 32 rows x 516 words
#define SW_STG  16512    // stage: 256 x 33 floats
#define SW_W1RU 24960
#define SW_W2RU 25536
#define SW_W1CP 26560
#define SW_W2CP 26848
#define SW_B1RU 27360
#define SW_B2RU 27392
#define SW_B1CP 27424
#define SW_B2CP 27440
#define SW_GCNW 27456
#define SW_GCNB 27488
#define SMEM_WORDS 27490
#define SMEM_BYTES (SMEM_WORDS * 4 + 8)

__device__ __forceinline__ float sigf(float x) { return 1.0f / (1.0f + expf(-x)); }

__device__ __forceinline__ void cpa16s(unsigned* sm, const void* gm) {
    unsigned sa = (unsigned)__cvta_generic_to_shared(sm);
    asm volatile("cp.async.cg.shared.global [%0], [%1], 16;" :: "r"(sa), "l"(gm) : "memory");
}
#define CP_COMMIT() asm volatile("cp.async.commit_group;" ::: "memory")
#define CP_WAIT(n)  asm volatile("cp.async.wait_group %0;" :: "n"(n) : "memory")

__device__ __forceinline__ unsigned long long dup2(float x) {
    unsigned long long r; unsigned u = __float_as_uint(x);
    asm("mov.b64 %0, {%1, %1};" : "=l"(r) : "r"(u));
    return r;
}
__device__ __forceinline__ void fma2(unsigned long long& s, unsigned long long a, unsigned long long w) {
    asm("fma.rn.f32x2 %0, %1, %2, %0;" : "+l"(s) : "l"(a), "l"(w));
}
__device__ __forceinline__ void unpack2(unsigned long long s, float& x, float& y) {
    unsigned lo, hi; asm("mov.b64 {%0, %1}, %2;" : "=r"(lo), "=r"(hi) : "l"(s));
    x = __uint_as_float(lo); y = __uint_as_float(hi);
}
__device__ __forceinline__ unsigned packbf2(float2 v) {
    __nv_bfloat162 b = __float22bfloat162_rn(v);
    return *(unsigned*)&b;
}

// per-batch barrier (R7-proven: all-thread gpu fence before the quorum)
__device__ __forceinline__ void batchbar(int b) {
    __threadfence();
    __syncthreads();
    if (threadIdx.x == 0) {
        unsigned gen = g_bgen[b * 32];
        if (atomicAdd(&g_bcnt[b * 32], 1) == GRP - 1) {
            g_bcnt[b * 32] = 0;
            __threadfence();
            g_bgen[b * 32] = gen + 1;
        } else {
            while (g_bgen[b * 32] == gen) __nanosleep(32);
        }
        __threadfence();
    }
    __syncthreads();
}

// ---------- GEMM phase: acc[256 own rows x C] = A_own(256x1024) @ X^T(C x 1024)^T ----------
// X^T loaded whole into smem once; A streamed per-warp via LDG.128 from the
// fragment-ordered pack with a depth-4 register ring (8 outstanding loads/warp).
template <int C>
__device__ __forceinline__ void gemmL(const uint4* __restrict__ Apk,
                                      const __nv_bfloat16* __restrict__ Xb,
                                      unsigned* smem_u, float acc[2][C / 8][4]) {
    const int tid = threadIdx.x, w = tid >> 5, lane = tid & 31;
    unsigned* Xs = smem_u + SW_X;

    // load full X^T (C rows x 2KB) into smem
#pragma unroll
    for (int q = 0; q < C / 2; q++) {
        int i = tid + q * 256;
        int c = i >> 7, ch = i & 127;
        cpa16s(Xs + c * XPW + ch * 4, Xb + (size_t)c * NN + ch * 8);
    }
    CP_COMMIT();
    CP_WAIT(0);
    __syncthreads();

#pragma unroll
    for (int mt = 0; mt < 2; mt++)
#pragma unroll
        for (int nt = 0; nt < C / 8; nt++)
#pragma unroll
            for (int q = 0; q < 4; q++) acc[mt][nt][q] = 0.f;

    const unsigned xB = (unsigned)__cvta_generic_to_shared(Xs);
    const unsigned boff = ((unsigned)(lane & 7) * XPW + ((lane >> 3) & 1) * 4) * 4;
    const uint4* Aw0 = Apk + ((size_t)(w * 2) * 64) * 32 + lane;      // mt=0
    const uint4* Aw1 = Aw0 + 64 * 32;                                  // mt=1

    uint4 r0[4], r1[4];
#pragma unroll
    for (int p = 0; p < 4; p++) { r0[p] = Aw0[p * 32]; r1[p] = Aw1[p * 32]; }

    for (int kb = 0; kb < 16; kb++) {
#pragma unroll
        for (int q = 0; q < 4; q++) {
            const int ks = kb * 4 + q;
            unsigned bf[C / 8][2];
#pragma unroll
            for (int nt = 0; nt < C / 8; nt++) {
                unsigned ad = xB + boff + (unsigned)nt * 8 * XPW * 4 + (unsigned)ks * 32;
                asm volatile("ldmatrix.sync.aligned.m8n8.x2.shared.b16 {%0,%1}, [%2];"
                             : "=r"(bf[nt][0]), "=r"(bf[nt][1]) : "r"(ad));
            }
            uint4 fa0 = r0[q], fa1 = r1[q];
            if (kb < 15) {                                 // prefetch ks+4
                r0[q] = Aw0[(ks + 4) * 32];
                r1[q] = Aw1[(ks + 4) * 32];
            }
#pragma unroll
            for (int nt = 0; nt < C / 8; nt++) {
                asm volatile(
                    "mma.sync.aligned.m16n8k16.row.col.f32.bf16.bf16.f32 "
                    "{%0,%1,%2,%3},{%4,%5,%6,%7},{%8,%9},{%0,%1,%2,%3};"
                    : "+f"(acc[0][nt][0]), "+f"(acc[0][nt][1]),
                      "+f"(acc[0][nt][2]), "+f"(acc[0][nt][3])
                    : "r"(fa0.x), "r"(fa0.y), "r"(fa0.z), "r"(fa0.w),
                      "r"(bf[nt][0]), "r"(bf[nt][1]));
                asm volatile(
                    "mma.sync.aligned.m16n8k16.row.col.f32.bf16.bf16.f32 "
                    "{%0,%1,%2,%3},{%4,%5,%6,%7},{%8,%9},{%0,%1,%2,%3};"
                    : "+f"(acc[1][nt][0]), "+f"(acc[1][nt][1]),
                      "+f"(acc[1][nt][2]), "+f"(acc[1][nt][3])
                    : "r"(fa1.x), "r"(fa1.y), "r"(fa1.z), "r"(fa1.w),
                      "r"(bf[nt][0]), "r"(bf[nt][1]));
            }
        }
    }
}

// write acc fragments to smem stage (256 rows, pitch 33)
template <int C>
__device__ __forceinline__ void stageStore(float* stage, const float acc[2][C / 8][4]) {
    const int lane = threadIdx.x & 31, w = threadIdx.x >> 5;
    const int g = lane >> 2, c2 = (lane & 3) * 2;
#pragma unroll
    for (int mt = 0; mt < 2; mt++) {
        int rr = w * 32 + mt * 16 + g;
#pragma unroll
        for (int nt = 0; nt < C / 8; nt++) {
            int col = nt * 8 + c2;
            stage[rr * 33 + col]           = acc[mt][nt][0];
            stage[rr * 33 + col + 1]       = acc[mt][nt][1];
            stage[(rr + 8) * 33 + col]     = acc[mt][nt][2];
            stage[(rr + 8) * 33 + col + 1] = acc[mt][nt][3];
        }
    }
}

// ================= persistent kernel =================
__global__ void __launch_bounds__(NTHR, 1) persistK(
    const float* __restrict__ A, const float* __restrict__ recent,
    const float* __restrict__ g1rW, const float* __restrict__ g1rb,
    const float* __restrict__ g1uW, const float* __restrict__ g1ub,
    const float* __restrict__ g1cW, const float* __restrict__ g1cb,
    const float* __restrict__ g2rW, const float* __restrict__ g2rb,
    const float* __restrict__ g2uW, const float* __restrict__ g2ub,
    const float* __restrict__ g2cW, const float* __restrict__ g2cb,
    const float* __restrict__ gcnW, const float* __restrict__ gcnb,
    float* __restrict__ out) {
    extern __shared__ unsigned smem_u[];
    float* stage = (float*)(smem_u + SW_STG);

    const int tid = threadIdx.x, w = tid >> 5, lane = tid & 31;
    const int b = blockIdx.x >> 2, rb = blockIdx.x & 3;
    const int row0 = rb * 256, n0 = row0 + tid;
    const size_t r0 = (size_t)b * NN + n0;

    // ---- weight tables into smem ----
    {
        float2* W1 = (float2*)(smem_u + SW_W1RU);
        for (int i = tid; i < 288; i += NTHR) W1[i] = make_float2(g1rW[i], g1uW[i]);
        float2* W2 = (float2*)(smem_u + SW_W2RU);
        for (int i = tid; i < 512; i += NTHR) W2[i] = make_float2(g2rW[i], g2uW[i]);
        float2* C1 = (float2*)(smem_u + SW_W1CP);
        for (int i = tid; i < 144; i += NTHR) {
            int k = i >> 3, m = i & 7;
            C1[i] = make_float2(g1cW[(2 * m) * 18 + k], g1cW[(2 * m + 1) * 18 + k]);
        }
        float2* C2 = (float2*)(smem_u + SW_W2CP);
        for (int i = tid; i < 256; i += NTHR) {
            int k = i >> 3, m = i & 7;
            C2[i] = make_float2(g2cW[(2 * m) * 32 + k], g2cW[(2 * m + 1) * 32 + k]);
        }
        if (tid < 16) ((float2*)(smem_u + SW_B1RU))[tid] = make_float2(g1rb[tid], g1ub[tid]);
        else if (tid < 32) ((float2*)(smem_u + SW_B2RU))[tid - 16] = make_float2(g2rb[tid - 16], g2ub[tid - 16]);
        else if (tid < 40) ((float2*)(smem_u + SW_B1CP))[tid - 32] = make_float2(g1cb[2 * (tid - 32)], g1cb[2 * (tid - 32) + 1]);
        else if (tid < 48) ((float2*)(smem_u + SW_B2CP))[tid - 40] = make_float2(g2cb[2 * (tid - 40)], g2cb[2 * (tid - 40) + 1]);
        else if (tid < 80) { int i = tid - 48; ((float*)(smem_u + SW_GCNW))[i] = gcnW[(i >> 4) * 80 + (i & 15)]; }
        else if (tid < 82) ((float*)(smem_u + SW_GCNB))[tid - 80] = gcnb[tid - 80];
    }

    // ---- pack own A slice into mma-fragment order (bf16) ----
    const float* Arow = A + ((size_t)b * NN + row0) * NN;
    uint4* pk = d_Apk + (size_t)blockIdx.x * 32768;
    {
        const int gr = lane >> 2, k0b = (lane & 3) * 2;
        for (int blk = w; blk < 16; blk += 8) {
            int rowbase = (blk >> 1) * 32 + (blk & 1) * 16;
            const float* rp0 = Arow + (size_t)(rowbase + gr) * NN;
            const float* rp8 = Arow + (size_t)(rowbase + gr + 8) * NN;
            for (int ks = 0; ks < 64; ks++) {
                int k0 = ks * 16 + k0b;
                uint4 u;
                u.x = packbf2(*(const float2*)(rp0 + k0));
                u.y = packbf2(*(const float2*)(rp8 + k0));
                u.z = packbf2(*(const float2*)(rp0 + k0 + 8));
                u.w = packbf2(*(const float2*)(rp8 + k0 + 8));
                pk[((size_t)blk * 64 + ks) * 32 + lane] = u;
            }
        }
    }

    // ---- exact fp32 rowsum (warp per row) ----
    for (int j = 0; j < 32; j++) {
        const int r = w * 32 + j;
        const float4* ap = (const float4*)(Arow + (size_t)r * NN);
        float s = 0.f;
#pragma unroll 4
        for (int q = lane; q < 256; q += 32) {
            float4 v = ap[q];
            s += (v.x + v.y) + (v.z + v.w);
        }
#pragma unroll
        for (int o = 16; o; o >>= 1) s += __shfl_xor_sync(~0u, s, o);
        if (!lane) d_scratch[OFF_RS + (size_t)b * NN + row0 + r] = s;
    }

    // ---- gather x_t (transposed bf16) + zero h columns ----
    {
        const float2* rp = (const float2*)recent;
        for (int t = 0; t < TT; t++) {
            float2 v = rp[(size_t)(b * TT + t) * NN + n0];
            d_xt[((size_t)b * 48 + 2 * t) * NN + n0]     = __float2bfloat16_rn(v.x);
            d_xt[((size_t)b * 48 + 2 * t + 1) * NN + n0] = __float2bfloat16_rn(v.y);
        }
        __nv_bfloat16 z = __float2bfloat16_rn(0.f);
        for (int c = 0; c < 32; c++) d_xbf[((size_t)b * 48 + c) * NN + n0] = z;
    }

    float h1[16], h2[16], uu[16], ah2s[16], ah1p[16];
#pragma unroll
    for (int k = 0; k < 16; k++) { h1[k] = 0.f; h2[k] = 0.f; }

    batchbar(b);

    // ---- A @ x_t for all 24 timesteps (CTA-local outputs) ----
    for (int g = 0; g < 3; g++) {
        float a16[2][2][4];
        gemmL<16>(pk, d_xt + ((size_t)b * 48 + g * 16) * NN, smem_u, a16);
        stageStore<16>(stage, a16);
        __syncthreads();
        float* axp = d_scratch + OFF_AX + (size_t)g * (BB * NN * 16) + r0 * 16;
        const float* srow = stage + tid * 33;
#pragma unroll
        for (int q = 0; q < 4; q++)
            ((float4*)axp)[q] = make_float4(srow[4 * q], srow[4 * q + 1], srow[4 * q + 2], srow[4 * q + 3]);
        __syncthreads();
    }

    const __nv_bfloat16* xbB = d_xbf + (size_t)b * 48 * NN;
    __nv_bfloat16* xo_h1 = d_xbf + ((size_t)b * 48 + 0) * NN + n0;
    __nv_bfloat16* xo_h2 = d_xbf + ((size_t)b * 48 + 16) * NN + n0;
    __nv_bfloat16* xo_rh = d_xbf + ((size_t)b * 48 + 32) * NN + n0;

    const unsigned long long* W1ru = (const unsigned long long*)(smem_u + SW_W1RU);
    const unsigned long long* W2ru = (const unsigned long long*)(smem_u + SW_W2RU);
    const unsigned long long* W1cp = (const unsigned long long*)(smem_u + SW_W1CP);
    const unsigned long long* W2cp = (const unsigned long long*)(smem_u + SW_W2CP);
    const unsigned long long* B1ru = (const unsigned long long*)(smem_u + SW_B1RU);
    const unsigned long long* B2ru = (const unsigned long long*)(smem_u + SW_B2RU);
    const unsigned long long* B1cp = (const unsigned long long*)(smem_u + SW_B1CP);
    const unsigned long long* B2cp = (const unsigned long long*)(smem_u + SW_B2CP);

    for (int t = 0; t < TT; t++) {
        const int g = t >> 3, p = t & 7;
        const float* axp = d_scratch + OFF_AX + (size_t)g * (BB * NN * 16) + r0 * 16 + p * 2;

        // ---- phase 1: [A@h1 | A@h2], gates1 ----
        {
            float a32[2][4][4];
            gemmL<32>(pk, xbB, smem_u, a32);
            stageStore<32>(stage, a32);
            __syncthreads();
            const float* srow = stage + tid * 33;
            float2 axv = *(const float2*)axp;
            float xh[18];
            xh[0] = axv.x; xh[1] = axv.y;
#pragma unroll
            for (int k = 0; k < 16; k++) { xh[2 + k] = srow[k]; ah2s[k] = srow[16 + k]; }
#pragma unroll
            for (int j = 0; j < 16; j++) {
                unsigned long long s = B1ru[j];
#pragma unroll
                for (int k = 0; k < 18; k++) fma2(s, dup2(xh[k]), W1ru[j * 18 + k]);
                float sr, su; unpack2(s, sr, su);
                uu[j] = sigf(su);
                xo_rh[(size_t)j * NN] = __float2bfloat16_rn(sigf(sr) * h1[j]);
            }
            __syncthreads();
        }
        batchbar(b);

        // ---- phase 2: A@(r1*h1), gates2 -> h1' ----
        {
            float a16[2][2][4];
            gemmL<16>(pk, xbB + (size_t)32 * NN, smem_u, a16);
            stageStore<16>(stage, a16);
            __syncthreads();
            const float* srow = stage + tid * 33;
            float2 axv = *(const float2*)axp;
            float xh[18];
            xh[0] = axv.x; xh[1] = axv.y;
#pragma unroll
            for (int k = 0; k < 16; k++) xh[2 + k] = srow[k];
            unsigned long long sm[8];
#pragma unroll
            for (int m = 0; m < 8; m++) sm[m] = B1cp[m];
#pragma unroll
            for (int k = 0; k < 18; k++) {
                unsigned long long a = dup2(xh[k]);
#pragma unroll
                for (int m = 0; m < 8; m++) fma2(sm[m], a, W1cp[k * 8 + m]);
            }
#pragma unroll
            for (int m = 0; m < 8; m++) {
                float c0, c1; unpack2(sm[m], c0, c1);
                int j = 2 * m;
                h1[j]     = uu[j]     * h1[j]     + (1.f - uu[j])     * tanhf(c0);
                h1[j + 1] = uu[j + 1] * h1[j + 1] + (1.f - uu[j + 1]) * tanhf(c1);
                xo_h1[(size_t)j * NN]       = __float2bfloat16_rn(h1[j]);
                xo_h1[(size_t)(j + 1) * NN] = __float2bfloat16_rn(h1[j + 1]);
            }
            __syncthreads();
        }
        batchbar(b);

        // ---- phase 3: A@h1', gates3 ----
        {
            float a16[2][2][4];
            gemmL<16>(pk, xbB, smem_u, a16);
            stageStore<16>(stage, a16);
            __syncthreads();
            const float* srow = stage + tid * 33;
#pragma unroll
            for (int k = 0; k < 16; k++) ah1p[k] = srow[k];
#pragma unroll
            for (int j = 0; j < 16; j++) {
                unsigned long long s = B2ru[j];
#pragma unroll
                for (int k = 0; k < 16; k++) fma2(s, dup2(ah1p[k]), W2ru[j * 32 + k]);
#pragma unroll
                for (int k = 0; k < 16; k++) fma2(s, dup2(ah2s[k]), W2ru[j * 32 + 16 + k]);
                float sr, su; unpack2(s, sr, su);
                uu[j] = sigf(su);
                xo_rh[(size_t)j * NN] = __float2bfloat16_rn(sigf(sr) * h2[j]);
            }
            __syncthreads();
        }
        batchbar(b);

        // ---- phase 4: A@(r2*h2), gates4 -> h2' ----
        {
            float a16[2][2][4];
            gemmL<16>(pk, xbB + (size_t)32 * NN, smem_u, a16);
            stageStore<16>(stage, a16);
            __syncthreads();
            const float* srow = stage + tid * 33;
            unsigned long long sm[8];
#pragma unroll
            for (int m = 0; m < 8; m++) sm[m] = B2cp[m];
#pragma unroll
            for (int k = 0; k < 16; k++) {
                unsigned long long a = dup2(ah1p[k]);
#pragma unroll
                for (int m = 0; m < 8; m++) fma2(sm[m], a, W2cp[k * 8 + m]);
            }
#pragma unroll
            for (int k = 0; k < 16; k++) {
                unsigned long long a = dup2(srow[k]);
#pragma unroll
                for (int m = 0; m < 8; m++) fma2(sm[m], a, W2cp[(16 + k) * 8 + m]);
            }
#pragma unroll
            for (int m = 0; m < 8; m++) {
                float c0, c1; unpack2(sm[m], c0, c1);
                int j = 2 * m;
                h2[j]     = uu[j]     * h2[j]     + (1.f - uu[j])     * tanhf(c0);
                h2[j + 1] = uu[j + 1] * h2[j + 1] + (1.f - uu[j + 1]) * tanhf(c1);
                xo_h2[(size_t)j * NN]       = __float2bfloat16_rn(h2[j]);
                xo_h2[(size_t)(j + 1) * NN] = __float2bfloat16_rn(h2[j + 1]);
            }
            __syncthreads();
        }
        batchbar(b);
    }

    // ---- final: A@h2 + folded trend/feat, tanh, write output ----
    {
        float a16[2][2][4];
        gemmL<16>(pk, xbB + (size_t)16 * NN, smem_u, a16);
        stageStore<16>(stage, a16);
        __syncthreads();
        const float* srow = stage + tid * 33;
        const float* gw = (const float*)(smem_u + SW_GCNW);
        const float* gb = (const float*)(smem_u + SW_GCNB);
        float rs = d_scratch[OFF_RS + r0];
        float o0 = gb[0] + rs * d_scratch[OFF_TVF + b * 2];
        float o1 = gb[1] + rs * d_scratch[OFF_TVF + b * 2 + 1];
#pragma unroll
        for (int c = 0; c < 16; c++) {
            o0 += srow[c] * gw[c];
            o1 += srow[c] * gw[16 + c];
        }
        *(float2*)(out + r0 * 2) = make_float2(tanhf(o0), tanhf(o1));
    }
}

// ---- 2-layer LSTM + feat FF folded into tvf (B,2) ----
__global__ __launch_bounds__(1024) void prepK(
    const float* __restrict__ trend, const float* __restrict__ tf,
    const float* __restrict__ Wih0, const float* __restrict__ Whh0,
    const float* __restrict__ bih0, const float* __restrict__ bhh0,
    const float* __restrict__ Wih1, const float* __restrict__ Whh1,
    const float* __restrict__ bih1, const float* __restrict__ bhh1,
    const float* __restrict__ ffW, const float* __restrict__ ffb,
    const float* __restrict__ gcnW) {
    __shared__ float h1s[32][32], c1s[32][32], h2s[32][32], c2s[32][32], feats[32][32];
    int tid = threadIdx.x;
    int b = tid >> 5, j = tid & 31;
    h1s[b][j] = 0.f; c1s[b][j] = 0.f; h2s[b][j] = 0.f; c2s[b][j] = 0.f;
    __syncthreads();

    for (int t = 0; t < TT; t++) {
        float x0 = trend[(b * TT + t) * 2 + 0];
        float x1 = trend[(b * TT + t) * 2 + 1];
        float g0[4];
#pragma unroll
        for (int g = 0; g < 4; g++) {
            int idx = g * 32 + j;
            float s = bih0[idx] + bhh0[idx] + Wih0[idx * 2] * x0 + Wih0[idx * 2 + 1] * x1;
            for (int k = 0; k < 32; k++) s += Whh0[idx * 32 + k] * h1s[b][k];
            g0[g] = s;
        }
        float c1 = sigf(g0[1]) * c1s[b][j] + sigf(g0[0]) * tanhf(g0[2]);
        float h1 = sigf(g0[3]) * tanhf(c1);
        __syncthreads();
        h1s[b][j] = h1; c1s[b][j] = c1;
        __syncthreads();

        float g1[4];
#pragma unroll
        for (int g = 0; g < 4; g++) {
            int idx = g * 32 + j;
            float s = bih1[idx] + bhh1[idx];
            for (int k = 0; k < 32; k++)
                s += Wih1[idx * 32 + k] * h1s[b][k] + Whh1[idx * 32 + k] * h2s[b][k];
            g1[g] = s;
        }
        float c2 = sigf(g1[1]) * c2s[b][j] + sigf(g1[0]) * tanhf(g1[2]);
        float h2 = sigf(g1[3]) * tanhf(c2);
        __syncthreads();
        h2s[b][j] = h2; c2s[b][j] = c2;
        __syncthreads();
    }

    float s = ffb[j];
    for (int k = 0; k < 31; k++) s += tf[b * 31 + k] * ffW[j * 31 + k];
    feats[b][j] = fmaxf(s, 0.f);
    __syncthreads();

    if (tid < 64) {
        int bb = tid >> 1, f = tid & 1;
        float s2 = 0.f;
        for (int c = 0; c < 32; c++)
            s2 += h2s[bb][c] * gcnW[f * 80 + 16 + c] + feats[bb][c] * gcnW[f * 80 + 48 + c];
        d_scratch[OFF_TVF + bb * 2 + f] = s2;
    }
}

// ================================== launcher ===================================
extern "C" void kernel_launch(void* const* d_in, const int* in_sizes, int n_in,
                              void* d_out, int out_size) {
    const float* recent = (const float*)d_in[0];
    const float* trend  = (const float*)d_in[1];
    const float* A      = (const float*)d_in[2];
    const float* tf     = (const float*)d_in[3];
    const float* g1rW = (const float*)d_in[4],  *g1rb = (const float*)d_in[5];
    const float* g1uW = (const float*)d_in[6],  *g1ub = (const float*)d_in[7];
    const float* g1cW = (const float*)d_in[8],  *g1cb = (const float*)d_in[9];
    const float* g2rW = (const float*)d_in[10], *g2rb = (const float*)d_in[11];
    const float* g2uW = (const float*)d_in[12], *g2ub = (const float*)d_in[13];
    const float* g2cW = (const float*)d_in[14], *g2cb = (const float*)d_in[15];
    const float* Wih0 = (const float*)d_in[16], *Whh0 = (const float*)d_in[17];
    const float* bih0 = (const float*)d_in[18], *bhh0 = (const float*)d_in[19];
    const float* Wih1 = (const float*)d_in[20], *Whh1 = (const float*)d_in[21];
    const float* bih1 = (const float*)d_in[22], *bhh1 = (const float*)d_in[23];
    const float* ffW  = (const float*)d_in[24], *ffb  = (const float*)d_in[25];
    const float* gcnW = (const float*)d_in[26], *gcnb = (const float*)d_in[27];
    float* out = (float*)d_out;

    cudaFuncSetAttribute(persistK, cudaFuncAttributeMaxDynamicSharedMemorySize, SMEM_BYTES);

    prepK<<<1, 1024>>>(trend, tf, Wih0, Whh0, bih0, bhh0,
                       Wih1, Whh1, bih1, bhh1, ffW, ffb, gcnW);
    persistK<<<NCTA, NTHR, SMEM_BYTES>>>(A, recent,
                                         g1rW, g1rb, g1uW, g1ub, g1cW, g1cb,
                                         g2rW, g2rb, g2uW, g2ub, g2cW, g2cb,
                                         gcnW, gcnb, out);
}